// round 7
// baseline (speedup 1.0000x reference)
#include <cuda_runtime.h>
#include <math.h>
#include <stdint.h>

// Problem constants
#define BB   8
#define CC   256
#define HW   4096
#define HW4  1024
#define EPSV 1e-5f

// D(16x8,f32) += A(16x8,tf32) * B(8x8,tf32)
// Operands carry raw fp32 bits; HW uses the 19 tf32 bits (truncation).
__device__ __forceinline__ void mma_tf32(float* c, const uint32_t* a, uint32_t b0, uint32_t b1) {
    asm volatile(
        "mma.sync.aligned.m16n8k8.row.col.f32.tf32.tf32.f32 "
        "{%0,%1,%2,%3}, {%4,%5,%6,%7}, {%8,%9}, {%0,%1,%2,%3};"
        : "+f"(c[0]), "+f"(c[1]), "+f"(c[2]), "+f"(c[3])
        : "r"(a[0]), "r"(a[1]), "r"(a[2]), "r"(a[3]), "r"(b0), "r"(b1));
}

// ---------------- scratch (static __device__ — allocation-free) ----------------
__device__ float g_g  [BB * 32 * HW];          //  4 MB  conv2 (g)  [b][k][m]
__device__ float g_f  [BB * 32 * HW4];         //  1 MB  pooled f   [b][k][n]
__device__ float g_hh [BB * 128 * HW4];        //  4 MB  pooled hh  [b][c][n]
__device__ float g_oT [(size_t)BB * HW * 128]; // 16 MB  oT         [b][m][c]

// ---------------------------------------------------------------------------
// Kernel 1: fused conv1/conv2/conv3 (1x1 conv + BN + ReLU) on tensor cores.
// grid (16 pixtiles, 6 sel, 8 b), 256 thr = 8 warps.
// CTA tile: 32 oc x 256 pix, K=256 in chunks of 32. Raw fp32 staging
// (LDG.128 -> STS.128), conflict-free fragment strides (w:36, x:264).
// ---------------------------------------------------------------------------
__global__ __launch_bounds__(256) void conv123_mma_kernel(
    const float* __restrict__ x,
    const float* __restrict__ w1, const float* __restrict__ b1, const float* __restrict__ s1,
    const float* __restrict__ t1, const float* __restrict__ m1, const float* __restrict__ v1,
    const float* __restrict__ w2, const float* __restrict__ b2, const float* __restrict__ s2,
    const float* __restrict__ t2, const float* __restrict__ m2, const float* __restrict__ v2,
    const float* __restrict__ w3, const float* __restrict__ b3, const float* __restrict__ s3,
    const float* __restrict__ t3, const float* __restrict__ m3, const float* __restrict__ v3)
{
    __shared__ __align__(16) uint32_t w_s[32 * 36];    // [oc][k], bank 4r+q
    __shared__ __align__(16) uint32_t x_s[32 * 264];   // [k][pix], bank 8q+r; reused as y_s

    int sel = blockIdx.y;
    const float *w, *pb, *ps, *pt, *pm, *pv;
    int oc0;
    if (sel == 0)      { w = w1; pb = b1; ps = s1; pt = t1; pm = m1; pv = v1; oc0 = 0; }
    else if (sel == 1) { w = w2; pb = b2; ps = s2; pt = t2; pm = m2; pv = v2; oc0 = 0; }
    else               { w = w3; pb = b3; ps = s3; pt = t3; pm = m3; pv = v3; oc0 = (sel - 2) * 32; }

    int b  = blockIdx.z;
    int p0 = blockIdx.x * 256;
    int tid = threadIdx.x, lane = tid & 31, warp = tid >> 5;
    int q = lane & 3, r = lane >> 2;

    const float* xb = x + (size_t)b * CC * HW + p0;

    float acc[2][4][4];
#pragma unroll
    for (int mt = 0; mt < 2; mt++)
#pragma unroll
        for (int nc = 0; nc < 4; nc++)
#pragma unroll
            for (int i = 0; i < 4; i++) acc[mt][nc][i] = 0.f;

    for (int kc0 = 0; kc0 < CC; kc0 += 32) {
        // stage w chunk [32oc][32k] raw bits
        {
            int oc = tid >> 3, kg = tid & 7;
            *(uint4*)&w_s[oc * 36 + kg * 4] =
                *(const uint4*)&w[(size_t)(oc0 + oc) * CC + kc0 + kg * 4];
        }
        // stage x chunk [32k][256pix] raw bits
#pragma unroll
        for (int j = 0; j < 8; j++) {
            int e = tid + 256 * j;
            int k = e >> 6, p4 = e & 63;
            *(uint4*)&x_s[k * 264 + p4 * 4] =
                *(const uint4*)&xb[(size_t)(kc0 + k) * HW + p4 * 4];
        }
        __syncthreads();

        int nbase = warp * 32 + r;
#pragma unroll
        for (int kc = 0; kc < 4; kc++) {
            uint32_t a[2][4];
#pragma unroll
            for (int mt = 0; mt < 2; mt++) {
                a[mt][0] = w_s[(mt * 16 + r) * 36 + kc * 8 + q];
                a[mt][1] = w_s[(mt * 16 + r + 8) * 36 + kc * 8 + q];
                a[mt][2] = w_s[(mt * 16 + r) * 36 + kc * 8 + q + 4];
                a[mt][3] = w_s[(mt * 16 + r + 8) * 36 + kc * 8 + q + 4];
            }
#pragma unroll
            for (int nc = 0; nc < 4; nc++) {
                uint32_t bb0 = x_s[(kc * 8 + q) * 264 + nbase + nc * 8];
                uint32_t bb1 = x_s[(kc * 8 + q + 4) * 264 + nbase + nc * 8];
                mma_tf32(acc[0][nc], a[0], bb0, bb1);
                mma_tf32(acc[1][nc], a[1], bb0, bb1);
            }
        }
        __syncthreads();
    }

    // ---- epilogue: BN(+ReLU) into smem staging (reuse x_s), then write out
    float* y_s = (float*)x_s;
    float gsc[2][2], gsh[2][2];
#pragma unroll
    for (int mt = 0; mt < 2; mt++)
#pragma unroll
        for (int h2 = 0; h2 < 2; h2++) {
            int oc = oc0 + mt * 16 + r + 8 * h2;
            float sc = ps[oc] * rsqrtf(pv[oc] + EPSV);
            gsc[mt][h2] = sc;
            gsh[mt][h2] = (pb[oc] - pm[oc]) * sc + pt[oc];
        }
#pragma unroll
    for (int mt = 0; mt < 2; mt++)
#pragma unroll
        for (int nc = 0; nc < 4; nc++) {
            int col = warp * 32 + nc * 8 + 2 * q;
            float2 v0 = make_float2(
                fmaxf(acc[mt][nc][0] * gsc[mt][0] + gsh[mt][0], 0.f),
                fmaxf(acc[mt][nc][1] * gsc[mt][0] + gsh[mt][0], 0.f));
            float2 v1 = make_float2(
                fmaxf(acc[mt][nc][2] * gsc[mt][1] + gsh[mt][1], 0.f),
                fmaxf(acc[mt][nc][3] * gsc[mt][1] + gsh[mt][1], 0.f));
            *(float2*)&y_s[(mt * 16 + r) * 264 + col]     = v0;
            *(float2*)&y_s[(mt * 16 + r + 8) * 264 + col] = v1;
        }
    __syncthreads();

    if (sel == 1) {
        float* op = g_g + (size_t)b * 32 * HW + p0;
#pragma unroll
        for (int j = 0; j < 32; j++) {
            int e = tid + 256 * j;
            int oc = e >> 8, pix = e & 255;
            op[(size_t)oc * HW + pix] = y_s[oc * 264 + pix];
        }
        return;
    }

    // pooled write (conv1 -> g_f, conv3 -> g_hh)
    int PR0 = p0 >> 7;
    float* outp = (sel == 0) ? (g_f + (size_t)b * 32 * HW4)
                             : (g_hh + (size_t)b * 128 * HW4 + (size_t)oc0 * HW4);
#pragma unroll
    for (int j = 0; j < 8; j++) {
        int e = tid + 256 * j;        // < 2048
        int ocl = e >> 6, qq = e & 63;
        int pq = qq >> 5, col = qq & 31;
        int base = ocl * 264 + pq * 128 + 2 * col;
        float v01 = fmaxf(y_s[base],      y_s[base + 1]);
        float v23 = fmaxf(y_s[base + 64], y_s[base + 65]);
        outp[(size_t)ocl * HW4 + (PR0 + pq) * 32 + col] = fmaxf(v01, v23);
    }
}

// ---------------------------------------------------------------------------
// Kernel 2: flash attention on tensor cores. Raw-bit staging (no cvt);
// hB filled with dense LDG.128 + rotated scatter (<=2-way STS conflicts).
// ---------------------------------------------------------------------------
__global__ __launch_bounds__(256) void flash_mma_kernel()
{
    __shared__ __align__(16) uint32_t fB[4][2][32][4];    //  4 KB (QK B: f)
    __shared__ __align__(16) uint32_t hB[16][2][32][4];   // 16 KB (PV B: hh)
    __shared__ __align__(16) uint32_t pS[8][16][36];      // 18 KB warp-private p

    int b = blockIdx.y, m0 = blockIdx.x * 128;
    int tid  = threadIdx.x;
    int lane = tid & 31, warp = tid >> 5;
    int q = lane & 3, r = lane >> 2;

    const float* gb = g_g  + (size_t)b * 32  * HW  + m0 + warp * 16;
    const float* fb = g_f  + (size_t)b * 32  * HW4;
    const float* hb = g_hh + (size_t)b * 128 * HW4;

    uint32_t gA[4][4];
#pragma unroll
    for (int kc = 0; kc < 4; kc++) {
        gA[kc][0] = __float_as_uint(gb[(size_t)(kc * 8 + q)     * HW + r]);
        gA[kc][1] = __float_as_uint(gb[(size_t)(kc * 8 + q)     * HW + r + 8]);
        gA[kc][2] = __float_as_uint(gb[(size_t)(kc * 8 + q + 4) * HW + r]);
        gA[kc][3] = __float_as_uint(gb[(size_t)(kc * 8 + q + 4) * HW + r + 8]);
    }

    float mx0 = -INFINITY, mx1 = -INFINITY, l0 = 0.f, l1 = 0.f;
    float acc[16][4];
#pragma unroll
    for (int cc = 0; cc < 16; cc++)
#pragma unroll
        for (int i = 0; i < 4; i++) acc[cc][i] = 0.f;

    for (int n0 = 0; n0 < HW4; n0 += 32) {
        // fB: scalar raw fill (small; conflict-free STS)
#pragma unroll
        for (int e = tid; e < 1024; e += 256) {
            int t_ = e & 3, ln = (e >> 2) & 31, ch = (e >> 7) & 1, nc = e >> 8;
            int k = (ln & 3) + 4 * (ch * 4 + t_);
            int n = nc * 8 + (ln >> 2);
            fB[nc][ch][ln][t_] = __float_as_uint(fb[(size_t)k * HW4 + n0 + n]);
        }
        // hB: dense LDG.128 along k, rotated scatter into fragment slots
#pragma unroll
        for (int j = 0; j < 4; j++) {
            int e = tid + 256 * j;          // 0..1023
            int k4 = e & 7, c = e >> 3;     // k0 = 4*k4, c 0..127
            int ch = k4 >> 2, t_ = k4 & 3;
            int cc = c >> 3, gl = c & 7;
            uint4 v = *(const uint4*)&hb[(size_t)c * HW4 + n0 + k4 * 4];
            uint32_t vv[4] = {v.x, v.y, v.z, v.w};
#pragma unroll
            for (int i = 0; i < 4; i++) {
                int ii = (i + gl) & 3;
                hB[cc][ch][4 * gl + ii][t_] = vv[ii];
            }
        }
        __syncthreads();

        float s[4][4];
#pragma unroll
        for (int nc = 0; nc < 4; nc++)
#pragma unroll
            for (int i = 0; i < 4; i++) s[nc][i] = 0.f;
#pragma unroll
        for (int nc = 0; nc < 4; nc++) {
            uint4 f0 = *(const uint4*)fB[nc][0][lane];
            uint4 f1 = *(const uint4*)fB[nc][1][lane];
            mma_tf32(s[nc], gA[0], f0.x, f0.y);
            mma_tf32(s[nc], gA[1], f0.z, f0.w);
            mma_tf32(s[nc], gA[2], f1.x, f1.y);
            mma_tf32(s[nc], gA[3], f1.z, f1.w);
        }

        float t0 = fmaxf(fmaxf(s[0][0], s[0][1]), fmaxf(s[1][0], s[1][1]));
        t0 = fmaxf(t0, fmaxf(fmaxf(s[2][0], s[2][1]), fmaxf(s[3][0], s[3][1])));
        float t1 = fmaxf(fmaxf(s[0][2], s[0][3]), fmaxf(s[1][2], s[1][3]));
        t1 = fmaxf(t1, fmaxf(fmaxf(s[2][2], s[2][3]), fmaxf(s[3][2], s[3][3])));
        t0 = fmaxf(t0, __shfl_xor_sync(0xffffffffu, t0, 1));
        t0 = fmaxf(t0, __shfl_xor_sync(0xffffffffu, t0, 2));
        t1 = fmaxf(t1, __shfl_xor_sync(0xffffffffu, t1, 1));
        t1 = fmaxf(t1, __shfl_xor_sync(0xffffffffu, t1, 2));
        float nm0 = fmaxf(mx0, t0), nm1 = fmaxf(mx1, t1);
        float fac0 = __expf(mx0 - nm0), fac1 = __expf(mx1 - nm1);
        mx0 = nm0; mx1 = nm1;

        float ps0 = 0.f, ps1 = 0.f;
#pragma unroll
        for (int nc = 0; nc < 4; nc++) {
            float e0 = __expf(s[nc][0] - mx0);
            float e1 = __expf(s[nc][1] - mx0);
            float e2 = __expf(s[nc][2] - mx1);
            float e3 = __expf(s[nc][3] - mx1);
            ps0 += e0 + e1; ps1 += e2 + e3;
            *(uint2*)&pS[warp][r]    [nc * 8 + 2 * q] =
                make_uint2(__float_as_uint(e0), __float_as_uint(e1));
            *(uint2*)&pS[warp][r + 8][nc * 8 + 2 * q] =
                make_uint2(__float_as_uint(e2), __float_as_uint(e3));
        }
        ps0 += __shfl_xor_sync(0xffffffffu, ps0, 1);
        ps0 += __shfl_xor_sync(0xffffffffu, ps0, 2);
        ps1 += __shfl_xor_sync(0xffffffffu, ps1, 1);
        ps1 += __shfl_xor_sync(0xffffffffu, ps1, 2);
        l0 = l0 * fac0 + ps0;
        l1 = l1 * fac1 + ps1;

#pragma unroll
        for (int cc = 0; cc < 16; cc++) {
            acc[cc][0] *= fac0; acc[cc][1] *= fac0;
            acc[cc][2] *= fac1; acc[cc][3] *= fac1;
        }

        __syncwarp();
        uint32_t pA[4][4];
#pragma unroll
        for (int kc = 0; kc < 4; kc++) {
            pA[kc][0] = pS[warp][r]    [kc * 8 + q];
            pA[kc][1] = pS[warp][r + 8][kc * 8 + q];
            pA[kc][2] = pS[warp][r]    [kc * 8 + q + 4];
            pA[kc][3] = pS[warp][r + 8][kc * 8 + q + 4];
        }

#pragma unroll
        for (int cc = 0; cc < 16; cc++) {
            uint4 h0 = *(const uint4*)hB[cc][0][lane];
            uint4 h1 = *(const uint4*)hB[cc][1][lane];
            mma_tf32(acc[cc], pA[0], h0.x, h0.y);
            mma_tf32(acc[cc], pA[1], h0.z, h0.w);
            mma_tf32(acc[cc], pA[2], h1.x, h1.y);
            mma_tf32(acc[cc], pA[3], h1.z, h1.w);
        }
        __syncthreads();
    }

    float rl0 = 1.f / l0, rl1 = 1.f / l1;
    float* ot = g_oT + ((size_t)b * HW + m0 + warp * 16) * 128;
#pragma unroll
    for (int cc = 0; cc < 16; cc++) {
        int c = cc * 8 + 2 * q;
        *(float2*)&ot[(size_t)r * 128 + c] =
            make_float2(acc[cc][0] * rl0, acc[cc][1] * rl0);
        *(float2*)&ot[(size_t)(r + 8) * 128 + c] =
            make_float2(acc[cc][2] * rl1, acc[cc][3] * rl1);
    }
}

// ---------------------------------------------------------------------------
// Kernel 3: out = gamma * BN(conv4(o)) + x, on tensor cores.
// grid (64 pixtiles, 2 octiles, 8 b), 256 thr = 8 warps.
// CTA: 128 oc x 64 pix, K=128. Raw staging, stride-36 conflict-free frags.
// ---------------------------------------------------------------------------
__global__ __launch_bounds__(256) void conv4_mma_kernel(
    const float* __restrict__ x,
    const float* __restrict__ w4, const float* __restrict__ b4, const float* __restrict__ s4,
    const float* __restrict__ t4, const float* __restrict__ m4, const float* __restrict__ v4,
    const float* __restrict__ gamma, float* __restrict__ out)
{
    __shared__ __align__(16) uint32_t w4_s[128 * 36];   // [oc][k] raw bits
    __shared__ __align__(16) uint32_t o_s [64 * 36];    // [pix][k] raw bits

    int b = blockIdx.z, oc0 = blockIdx.y * 128, p0 = blockIdx.x * 64;
    int tid = threadIdx.x, lane = tid & 31, warp = tid >> 5;
    int q = lane & 3, r = lane >> 2;

    const float* obT = g_oT + (size_t)b * HW * 128 + (size_t)p0 * 128;

    float acc[8][4];
#pragma unroll
    for (int nc = 0; nc < 8; nc++)
#pragma unroll
        for (int i = 0; i < 4; i++) acc[nc][i] = 0.f;

    for (int kc0 = 0; kc0 < 128; kc0 += 32) {
        // stage w4 chunk [128oc][32k]
#pragma unroll
        for (int j = 0; j < 4; j++) {
            int e = tid + 256 * j;
            int oc = e >> 3, kg = e & 7;
            *(uint4*)&w4_s[oc * 36 + kg * 4] =
                *(const uint4*)&w4[(size_t)(oc0 + oc) * 128 + kc0 + kg * 4];
        }
        // stage oT chunk [64pix][32k]
#pragma unroll
        for (int j = 0; j < 2; j++) {
            int e = tid + 256 * j;
            int n = e >> 3, kg = e & 7;
            *(uint4*)&o_s[n * 36 + kg * 4] =
                *(const uint4*)&obT[(size_t)n * 128 + kc0 + kg * 4];
        }
        __syncthreads();

#pragma unroll
        for (int kc = 0; kc < 4; kc++) {
            uint32_t a[4];
            a[0] = w4_s[(warp * 16 + r) * 36 + kc * 8 + q];
            a[1] = w4_s[(warp * 16 + r + 8) * 36 + kc * 8 + q];
            a[2] = w4_s[(warp * 16 + r) * 36 + kc * 8 + q + 4];
            a[3] = w4_s[(warp * 16 + r + 8) * 36 + kc * 8 + q + 4];
#pragma unroll
            for (int nc = 0; nc < 8; nc++) {
                uint32_t bb0 = o_s[(nc * 8 + r) * 36 + kc * 8 + q];
                uint32_t bb1 = o_s[(nc * 8 + r) * 36 + kc * 8 + q + 4];
                mma_tf32(acc[nc], a, bb0, bb1);
            }
        }
        __syncthreads();
    }

    float gm = *gamma;
    int ocA = oc0 + warp * 16 + r, ocB = ocA + 8;
    float scA = s4[ocA] * rsqrtf(v4[ocA] + EPSV);
    float shA = (b4[ocA] - m4[ocA]) * scA + t4[ocA];
    float scB = s4[ocB] * rsqrtf(v4[ocB] + EPSV);
    float shB = (b4[ocB] - m4[ocB]) * scB + t4[ocB];
    const float* xpA = x   + ((size_t)b * CC + ocA) * HW + p0;
    float*       opA = out + ((size_t)b * CC + ocA) * HW + p0;
    const float* xpB = xpA + 8 * HW;
    float*       opB = opA + 8 * HW;
#pragma unroll
    for (int nc = 0; nc < 8; nc++) {
        int pix = nc * 8 + 2 * q;
        *(float2*)&opA[pix] = make_float2(
            gm * (acc[nc][0] * scA + shA) + xpA[pix],
            gm * (acc[nc][1] * scA + shA) + xpA[pix + 1]);
        *(float2*)&opB[pix] = make_float2(
            gm * (acc[nc][2] * scB + shB) + xpB[pix],
            gm * (acc[nc][3] * scB + shB) + xpB[pix + 1]);
    }
}

// ---------------------------------------------------------------------------
extern "C" void kernel_launch(void* const* d_in, const int* in_sizes, int n_in,
                              void* d_out, int out_size)
{
    (void)in_sizes; (void)n_in; (void)out_size;
    const float* x = (const float*)d_in[0];
#define P(i) ((const float*)d_in[i])

    conv123_mma_kernel<<<dim3(16, 6, 8), 256>>>(
        x,
        P(1), P(2), P(3), P(4), P(5), P(6),        // conv1
        P(7), P(8), P(9), P(10), P(11), P(12),     // conv2
        P(13), P(14), P(15), P(16), P(17), P(18)); // conv3

    flash_mma_kernel<<<dim3(32, 8), 256>>>();

    conv4_mma_kernel<<<dim3(64, 2, 8), 256>>>(
        x, P(19), P(20), P(21), P(22), P(23), P(24), P(25), (float*)d_out);
#undef P
}

// round 8
// speedup vs baseline: 1.4241x; 1.4241x over previous
#include <cuda_runtime.h>
#include <math.h>
#include <stdint.h>

// Problem constants
#define BB   8
#define CC   256
#define HW   4096
#define HW4  1024
#define EPSV 1e-5f

// D(16x8,f32) += A(16x8,tf32) * B(8x8,tf32)
// Operands carry raw fp32 bits; HW uses the 19 tf32 bits (truncation).
__device__ __forceinline__ void mma_tf32(float* c, const uint32_t* a, uint32_t b0, uint32_t b1) {
    asm volatile(
        "mma.sync.aligned.m16n8k8.row.col.f32.tf32.tf32.f32 "
        "{%0,%1,%2,%3}, {%4,%5,%6,%7}, {%8,%9}, {%0,%1,%2,%3};"
        : "+f"(c[0]), "+f"(c[1]), "+f"(c[2]), "+f"(c[3])
        : "r"(a[0]), "r"(a[1]), "r"(a[2]), "r"(a[3]), "r"(b0), "r"(b1));
}

// ---------------- scratch (static __device__ — allocation-free) ----------------
__device__ float g_g  [BB * 32 * HW];          //  4 MB  conv2 (g)  [b][k][m]
__device__ float g_f  [BB * 32 * HW4];         //  1 MB  pooled f   [b][k][n]
__device__ float g_hh [BB * 128 * HW4];        //  4 MB  pooled hh  [b][c][n]
__device__ float g_oT [(size_t)BB * HW * 128]; // 16 MB  oT         [b][m][c]

// ---------------------------------------------------------------------------
// Kernel 1: fused conv1/conv2/conv3 (1x1 conv + BN + ReLU) on tensor cores.
// grid (16 pixtiles, 6 sel, 8 b), 256 thr = 8 warps.
// CTA tile: 32 oc x 256 pix, K=256 in chunks of 32. Raw fp32 staging
// (LDG.128 -> STS.128), conflict-free fragment strides (w:36, x:264).
// ---------------------------------------------------------------------------
__global__ __launch_bounds__(256) void conv123_mma_kernel(
    const float* __restrict__ x,
    const float* __restrict__ w1, const float* __restrict__ b1, const float* __restrict__ s1,
    const float* __restrict__ t1, const float* __restrict__ m1, const float* __restrict__ v1,
    const float* __restrict__ w2, const float* __restrict__ b2, const float* __restrict__ s2,
    const float* __restrict__ t2, const float* __restrict__ m2, const float* __restrict__ v2,
    const float* __restrict__ w3, const float* __restrict__ b3, const float* __restrict__ s3,
    const float* __restrict__ t3, const float* __restrict__ m3, const float* __restrict__ v3)
{
    __shared__ __align__(16) uint32_t w_s[32 * 36];    // [oc][k], bank 4r+q
    __shared__ __align__(16) uint32_t x_s[32 * 264];   // [k][pix], bank 8q+r; reused as y_s

    int sel = blockIdx.y;
    const float *w, *pb, *ps, *pt, *pm, *pv;
    int oc0;
    if (sel == 0)      { w = w1; pb = b1; ps = s1; pt = t1; pm = m1; pv = v1; oc0 = 0; }
    else if (sel == 1) { w = w2; pb = b2; ps = s2; pt = t2; pm = m2; pv = v2; oc0 = 0; }
    else               { w = w3; pb = b3; ps = s3; pt = t3; pm = m3; pv = v3; oc0 = (sel - 2) * 32; }

    int b  = blockIdx.z;
    int p0 = blockIdx.x * 256;
    int tid = threadIdx.x, lane = tid & 31, warp = tid >> 5;
    int q = lane & 3, r = lane >> 2;

    const float* xb = x + (size_t)b * CC * HW + p0;

    float acc[2][4][4];
#pragma unroll
    for (int mt = 0; mt < 2; mt++)
#pragma unroll
        for (int nc = 0; nc < 4; nc++)
#pragma unroll
            for (int i = 0; i < 4; i++) acc[mt][nc][i] = 0.f;

    for (int kc0 = 0; kc0 < CC; kc0 += 32) {
        // stage w chunk [32oc][32k] raw bits
        {
            int oc = tid >> 3, kg = tid & 7;
            *(uint4*)&w_s[oc * 36 + kg * 4] =
                *(const uint4*)&w[(size_t)(oc0 + oc) * CC + kc0 + kg * 4];
        }
        // stage x chunk [32k][256pix] raw bits
#pragma unroll
        for (int j = 0; j < 8; j++) {
            int e = tid + 256 * j;
            int k = e >> 6, p4 = e & 63;
            *(uint4*)&x_s[k * 264 + p4 * 4] =
                *(const uint4*)&xb[(size_t)(kc0 + k) * HW + p4 * 4];
        }
        __syncthreads();

        int nbase = warp * 32 + r;
#pragma unroll
        for (int kc = 0; kc < 4; kc++) {
            uint32_t a[2][4];
#pragma unroll
            for (int mt = 0; mt < 2; mt++) {
                a[mt][0] = w_s[(mt * 16 + r) * 36 + kc * 8 + q];
                a[mt][1] = w_s[(mt * 16 + r + 8) * 36 + kc * 8 + q];
                a[mt][2] = w_s[(mt * 16 + r) * 36 + kc * 8 + q + 4];
                a[mt][3] = w_s[(mt * 16 + r + 8) * 36 + kc * 8 + q + 4];
            }
#pragma unroll
            for (int nc = 0; nc < 4; nc++) {
                uint32_t bb0 = x_s[(kc * 8 + q) * 264 + nbase + nc * 8];
                uint32_t bb1 = x_s[(kc * 8 + q + 4) * 264 + nbase + nc * 8];
                mma_tf32(acc[0][nc], a[0], bb0, bb1);
                mma_tf32(acc[1][nc], a[1], bb0, bb1);
            }
        }
        __syncthreads();
    }

    // ---- epilogue: BN(+ReLU) into smem staging (reuse x_s), then write out
    float* y_s = (float*)x_s;
    float gsc[2][2], gsh[2][2];
#pragma unroll
    for (int mt = 0; mt < 2; mt++)
#pragma unroll
        for (int h2 = 0; h2 < 2; h2++) {
            int oc = oc0 + mt * 16 + r + 8 * h2;
            float sc = ps[oc] * rsqrtf(pv[oc] + EPSV);
            gsc[mt][h2] = sc;
            gsh[mt][h2] = (pb[oc] - pm[oc]) * sc + pt[oc];
        }
#pragma unroll
    for (int mt = 0; mt < 2; mt++)
#pragma unroll
        for (int nc = 0; nc < 4; nc++) {
            int col = warp * 32 + nc * 8 + 2 * q;
            float2 v0 = make_float2(
                fmaxf(acc[mt][nc][0] * gsc[mt][0] + gsh[mt][0], 0.f),
                fmaxf(acc[mt][nc][1] * gsc[mt][0] + gsh[mt][0], 0.f));
            float2 v1 = make_float2(
                fmaxf(acc[mt][nc][2] * gsc[mt][1] + gsh[mt][1], 0.f),
                fmaxf(acc[mt][nc][3] * gsc[mt][1] + gsh[mt][1], 0.f));
            *(float2*)&y_s[(mt * 16 + r) * 264 + col]     = v0;
            *(float2*)&y_s[(mt * 16 + r + 8) * 264 + col] = v1;
        }
    __syncthreads();

    if (sel == 1) {
        float* op = g_g + (size_t)b * 32 * HW + p0;
#pragma unroll
        for (int j = 0; j < 32; j++) {
            int e = tid + 256 * j;
            int oc = e >> 8, pix = e & 255;
            op[(size_t)oc * HW + pix] = y_s[oc * 264 + pix];
        }
        return;
    }

    // pooled write (conv1 -> g_f, conv3 -> g_hh)
    int PR0 = p0 >> 7;
    float* outp = (sel == 0) ? (g_f + (size_t)b * 32 * HW4)
                             : (g_hh + (size_t)b * 128 * HW4 + (size_t)oc0 * HW4);
#pragma unroll
    for (int j = 0; j < 8; j++) {
        int e = tid + 256 * j;        // < 2048
        int ocl = e >> 6, qq = e & 63;
        int pq = qq >> 5, col = qq & 31;
        int base = ocl * 264 + pq * 128 + 2 * col;
        float v01 = fmaxf(y_s[base],      y_s[base + 1]);
        float v23 = fmaxf(y_s[base + 64], y_s[base + 65]);
        outp[(size_t)ocl * HW4 + (PR0 + pq) * 32 + col] = fmaxf(v01, v23);
    }
}

// ---------------------------------------------------------------------------
// Kernel 2: flash attention on tensor cores. Raw-bit staging (no cvt),
// round-6 static-index fills (no dynamic register indexing).
// ---------------------------------------------------------------------------
__global__ __launch_bounds__(256) void flash_mma_kernel()
{
    __shared__ __align__(16) uint32_t fB[4][2][32][4];    //  4 KB (QK B: f)
    __shared__ __align__(16) uint32_t hB[16][2][32][4];   // 16 KB (PV B: hh)
    __shared__ __align__(16) uint32_t pS[8][16][36];      // 18 KB warp-private p

    int b = blockIdx.y, m0 = blockIdx.x * 128;
    int tid  = threadIdx.x;
    int lane = tid & 31, warp = tid >> 5;
    int q = lane & 3, r = lane >> 2;

    const float* gb = g_g  + (size_t)b * 32  * HW  + m0 + warp * 16;
    const float* fb = g_f  + (size_t)b * 32  * HW4;
    const float* hb = g_hh + (size_t)b * 128 * HW4;

    uint32_t gA[4][4];
#pragma unroll
    for (int kc = 0; kc < 4; kc++) {
        gA[kc][0] = __float_as_uint(gb[(size_t)(kc * 8 + q)     * HW + r]);
        gA[kc][1] = __float_as_uint(gb[(size_t)(kc * 8 + q)     * HW + r + 8]);
        gA[kc][2] = __float_as_uint(gb[(size_t)(kc * 8 + q + 4) * HW + r]);
        gA[kc][3] = __float_as_uint(gb[(size_t)(kc * 8 + q + 4) * HW + r + 8]);
    }

    float mx0 = -INFINITY, mx1 = -INFINITY, l0 = 0.f, l1 = 0.f;
    float acc[16][4];
#pragma unroll
    for (int cc = 0; cc < 16; cc++)
#pragma unroll
        for (int i = 0; i < 4; i++) acc[cc][i] = 0.f;

    for (int n0 = 0; n0 < HW4; n0 += 32) {
#pragma unroll
        for (int e = tid; e < 1024; e += 256) {
            int t_ = e & 3, ln = (e >> 2) & 31, ch = (e >> 7) & 1, nc = e >> 8;
            int k = (ln & 3) + 4 * (ch * 4 + t_);
            int n = nc * 8 + (ln >> 2);
            fB[nc][ch][ln][t_] = __float_as_uint(fb[(size_t)k * HW4 + n0 + n]);
        }
#pragma unroll
        for (int e = tid; e < 4096; e += 256) {
            int t_ = e & 3, ln = (e >> 2) & 31, ch = (e >> 7) & 1, cc = e >> 8;
            int k = (ln & 3) + 4 * (ch * 4 + t_);
            int c = cc * 8 + (ln >> 2);
            hB[cc][ch][ln][t_] = __float_as_uint(hb[(size_t)c * HW4 + n0 + k]);
        }
        __syncthreads();

        float s[4][4];
#pragma unroll
        for (int nc = 0; nc < 4; nc++)
#pragma unroll
            for (int i = 0; i < 4; i++) s[nc][i] = 0.f;
#pragma unroll
        for (int nc = 0; nc < 4; nc++) {
            uint4 f0 = *(const uint4*)fB[nc][0][lane];
            uint4 f1 = *(const uint4*)fB[nc][1][lane];
            mma_tf32(s[nc], gA[0], f0.x, f0.y);
            mma_tf32(s[nc], gA[1], f0.z, f0.w);
            mma_tf32(s[nc], gA[2], f1.x, f1.y);
            mma_tf32(s[nc], gA[3], f1.z, f1.w);
        }

        float t0 = fmaxf(fmaxf(s[0][0], s[0][1]), fmaxf(s[1][0], s[1][1]));
        t0 = fmaxf(t0, fmaxf(fmaxf(s[2][0], s[2][1]), fmaxf(s[3][0], s[3][1])));
        float t1 = fmaxf(fmaxf(s[0][2], s[0][3]), fmaxf(s[1][2], s[1][3]));
        t1 = fmaxf(t1, fmaxf(fmaxf(s[2][2], s[2][3]), fmaxf(s[3][2], s[3][3])));
        t0 = fmaxf(t0, __shfl_xor_sync(0xffffffffu, t0, 1));
        t0 = fmaxf(t0, __shfl_xor_sync(0xffffffffu, t0, 2));
        t1 = fmaxf(t1, __shfl_xor_sync(0xffffffffu, t1, 1));
        t1 = fmaxf(t1, __shfl_xor_sync(0xffffffffu, t1, 2));
        float nm0 = fmaxf(mx0, t0), nm1 = fmaxf(mx1, t1);
        float fac0 = __expf(mx0 - nm0), fac1 = __expf(mx1 - nm1);
        mx0 = nm0; mx1 = nm1;

        float ps0 = 0.f, ps1 = 0.f;
#pragma unroll
        for (int nc = 0; nc < 4; nc++) {
            float e0 = __expf(s[nc][0] - mx0);
            float e1 = __expf(s[nc][1] - mx0);
            float e2 = __expf(s[nc][2] - mx1);
            float e3 = __expf(s[nc][3] - mx1);
            ps0 += e0 + e1; ps1 += e2 + e3;
            *(uint2*)&pS[warp][r]    [nc * 8 + 2 * q] =
                make_uint2(__float_as_uint(e0), __float_as_uint(e1));
            *(uint2*)&pS[warp][r + 8][nc * 8 + 2 * q] =
                make_uint2(__float_as_uint(e2), __float_as_uint(e3));
        }
        ps0 += __shfl_xor_sync(0xffffffffu, ps0, 1);
        ps0 += __shfl_xor_sync(0xffffffffu, ps0, 2);
        ps1 += __shfl_xor_sync(0xffffffffu, ps1, 1);
        ps1 += __shfl_xor_sync(0xffffffffu, ps1, 2);
        l0 = l0 * fac0 + ps0;
        l1 = l1 * fac1 + ps1;

#pragma unroll
        for (int cc = 0; cc < 16; cc++) {
            acc[cc][0] *= fac0; acc[cc][1] *= fac0;
            acc[cc][2] *= fac1; acc[cc][3] *= fac1;
        }

        __syncwarp();
        uint32_t pA[4][4];
#pragma unroll
        for (int kc = 0; kc < 4; kc++) {
            pA[kc][0] = pS[warp][r]    [kc * 8 + q];
            pA[kc][1] = pS[warp][r + 8][kc * 8 + q];
            pA[kc][2] = pS[warp][r]    [kc * 8 + q + 4];
            pA[kc][3] = pS[warp][r + 8][kc * 8 + q + 4];
        }

#pragma unroll
        for (int cc = 0; cc < 16; cc++) {
            uint4 h0 = *(const uint4*)hB[cc][0][lane];
            uint4 h1 = *(const uint4*)hB[cc][1][lane];
            mma_tf32(acc[cc], pA[0], h0.x, h0.y);
            mma_tf32(acc[cc], pA[1], h0.z, h0.w);
            mma_tf32(acc[cc], pA[2], h1.x, h1.y);
            mma_tf32(acc[cc], pA[3], h1.z, h1.w);
        }
        __syncthreads();
    }

    float rl0 = 1.f / l0, rl1 = 1.f / l1;
    float* ot = g_oT + ((size_t)b * HW + m0 + warp * 16) * 128;
#pragma unroll
    for (int cc = 0; cc < 16; cc++) {
        int c = cc * 8 + 2 * q;
        *(float2*)&ot[(size_t)r * 128 + c] =
            make_float2(acc[cc][0] * rl0, acc[cc][1] * rl0);
        *(float2*)&ot[(size_t)(r + 8) * 128 + c] =
            make_float2(acc[cc][2] * rl1, acc[cc][3] * rl1);
    }
}

// ---------------------------------------------------------------------------
// Kernel 3: out = gamma * BN(conv4(o)) + x, on tensor cores.
// grid (64 pixtiles, 2 octiles, 8 b), 256 thr = 8 warps.
// CTA: 128 oc x 64 pix, K=128. Raw staging, stride-36 conflict-free frags.
// ---------------------------------------------------------------------------
__global__ __launch_bounds__(256) void conv4_mma_kernel(
    const float* __restrict__ x,
    const float* __restrict__ w4, const float* __restrict__ b4, const float* __restrict__ s4,
    const float* __restrict__ t4, const float* __restrict__ m4, const float* __restrict__ v4,
    const float* __restrict__ gamma, float* __restrict__ out)
{
    __shared__ __align__(16) uint32_t w4_s[128 * 36];   // [oc][k] raw bits
    __shared__ __align__(16) uint32_t o_s [64 * 36];    // [pix][k] raw bits

    int b = blockIdx.z, oc0 = blockIdx.y * 128, p0 = blockIdx.x * 64;
    int tid = threadIdx.x, lane = tid & 31, warp = tid >> 5;
    int q = lane & 3, r = lane >> 2;

    const float* obT = g_oT + (size_t)b * HW * 128 + (size_t)p0 * 128;

    float acc[8][4];
#pragma unroll
    for (int nc = 0; nc < 8; nc++)
#pragma unroll
        for (int i = 0; i < 4; i++) acc[nc][i] = 0.f;

    for (int kc0 = 0; kc0 < 128; kc0 += 32) {
        // stage w4 chunk [128oc][32k]
#pragma unroll
        for (int j = 0; j < 4; j++) {
            int e = tid + 256 * j;
            int oc = e >> 3, kg = e & 7;
            *(uint4*)&w4_s[oc * 36 + kg * 4] =
                *(const uint4*)&w4[(size_t)(oc0 + oc) * 128 + kc0 + kg * 4];
        }
        // stage oT chunk [64pix][32k]
#pragma unroll
        for (int j = 0; j < 2; j++) {
            int e = tid + 256 * j;
            int n = e >> 3, kg = e & 7;
            *(uint4*)&o_s[n * 36 + kg * 4] =
                *(const uint4*)&obT[(size_t)n * 128 + kc0 + kg * 4];
        }
        __syncthreads();

#pragma unroll
        for (int kc = 0; kc < 4; kc++) {
            uint32_t a[4];
            a[0] = w4_s[(warp * 16 + r) * 36 + kc * 8 + q];
            a[1] = w4_s[(warp * 16 + r + 8) * 36 + kc * 8 + q];
            a[2] = w4_s[(warp * 16 + r) * 36 + kc * 8 + q + 4];
            a[3] = w4_s[(warp * 16 + r + 8) * 36 + kc * 8 + q + 4];
#pragma unroll
            for (int nc = 0; nc < 8; nc++) {
                uint32_t bb0 = o_s[(nc * 8 + r) * 36 + kc * 8 + q];
                uint32_t bb1 = o_s[(nc * 8 + r) * 36 + kc * 8 + q + 4];
                mma_tf32(acc[nc], a, bb0, bb1);
            }
        }
        __syncthreads();
    }

    float gm = *gamma;
    int ocA = oc0 + warp * 16 + r, ocB = ocA + 8;
    float scA = s4[ocA] * rsqrtf(v4[ocA] + EPSV);
    float shA = (b4[ocA] - m4[ocA]) * scA + t4[ocA];
    float scB = s4[ocB] * rsqrtf(v4[ocB] + EPSV);
    float shB = (b4[ocB] - m4[ocB]) * scB + t4[ocB];
    const float* xpA = x   + ((size_t)b * CC + ocA) * HW + p0;
    float*       opA = out + ((size_t)b * CC + ocA) * HW + p0;
    const float* xpB = xpA + 8 * HW;
    float*       opB = opA + 8 * HW;
#pragma unroll
    for (int nc = 0; nc < 8; nc++) {
        int pix = nc * 8 + 2 * q;
        *(float2*)&opA[pix] = make_float2(
            gm * (acc[nc][0] * scA + shA) + xpA[pix],
            gm * (acc[nc][1] * scA + shA) + xpA[pix + 1]);
        *(float2*)&opB[pix] = make_float2(
            gm * (acc[nc][2] * scB + shB) + xpB[pix],
            gm * (acc[nc][3] * scB + shB) + xpB[pix + 1]);
    }
}

// ---------------------------------------------------------------------------
extern "C" void kernel_launch(void* const* d_in, const int* in_sizes, int n_in,
                              void* d_out, int out_size)
{
    (void)in_sizes; (void)n_in; (void)out_size;
    const float* x = (const float*)d_in[0];
#define P(i) ((const float*)d_in[i])

    conv123_mma_kernel<<<dim3(16, 6, 8), 256>>>(
        x,
        P(1), P(2), P(3), P(4), P(5), P(6),        // conv1
        P(7), P(8), P(9), P(10), P(11), P(12),     // conv2
        P(13), P(14), P(15), P(16), P(17), P(18)); // conv3

    flash_mma_kernel<<<dim3(32, 8), 256>>>();

    conv4_mma_kernel<<<dim3(64, 2, 8), 256>>>(
        x, P(19), P(20), P(21), P(22), P(23), P(24), P(25), (float*)d_out);
#undef P
}

// round 9
// speedup vs baseline: 1.7162x; 1.2052x over previous
#include <cuda_runtime.h>
#include <math.h>
#include <stdint.h>

// Problem constants
#define BB   8
#define CC   256
#define HW   4096
#define HW4  1024
#define EPSV 1e-5f

// D(16x8,f32) += A(16x8,tf32) * B(8x8,tf32)
// Operands carry raw fp32 bits; HW uses the 19 tf32 bits (truncation).
__device__ __forceinline__ void mma_tf32(float* c, const uint32_t* a, uint32_t b0, uint32_t b1) {
    asm volatile(
        "mma.sync.aligned.m16n8k8.row.col.f32.tf32.tf32.f32 "
        "{%0,%1,%2,%3}, {%4,%5,%6,%7}, {%8,%9}, {%0,%1,%2,%3};"
        : "+f"(c[0]), "+f"(c[1]), "+f"(c[2]), "+f"(c[3])
        : "r"(a[0]), "r"(a[1]), "r"(a[2]), "r"(a[3]), "r"(b0), "r"(b1));
}

// ---------------- scratch (static __device__ — allocation-free) ----------------
// g_f / g_hh are stored in flash's B-fragment order:
//   g_f : per b, 32 n-tiles of [nc=4][ch=2][ln=32][t_=4]  (1024 words/tile)
//   g_hh: per b, 32 n-tiles of [cc=16][ch=2][ln=32][t_=4] (4096 words/tile)
__device__ float g_g  [BB * 32 * HW];          //  4 MB  conv2 (g)  [b][k][m]
__device__ float g_f  [BB * 32 * HW4];         //  1 MB  pooled f   (frag order)
__device__ float g_hh [BB * 128 * HW4];        //  4 MB  pooled hh  (frag order)
__device__ float g_oT [(size_t)BB * HW * 128]; // 16 MB  oT         [b][m][c]

// ---------------------------------------------------------------------------
// Kernel 1: fused conv1/conv2/conv3 (1x1 conv + BN + ReLU) on tensor cores.
// grid (16 pixtiles, 6 sel, 8 b), 256 thr = 8 warps.
// CTA tile: 32 oc x 256 pix, K=256 in chunks of 32. Raw fp32 staging,
// conflict-free fragment strides (w:36, x:264). Pooled outputs are written
// directly in flash's fragment order.
// ---------------------------------------------------------------------------
__global__ __launch_bounds__(256) void conv123_mma_kernel(
    const float* __restrict__ x,
    const float* __restrict__ w1, const float* __restrict__ b1, const float* __restrict__ s1,
    const float* __restrict__ t1, const float* __restrict__ m1, const float* __restrict__ v1,
    const float* __restrict__ w2, const float* __restrict__ b2, const float* __restrict__ s2,
    const float* __restrict__ t2, const float* __restrict__ m2, const float* __restrict__ v2,
    const float* __restrict__ w3, const float* __restrict__ b3, const float* __restrict__ s3,
    const float* __restrict__ t3, const float* __restrict__ m3, const float* __restrict__ v3)
{
    __shared__ __align__(16) uint32_t w_s[32 * 36];    // [oc][k], bank 4r+q
    __shared__ __align__(16) uint32_t x_s[32 * 264];   // [k][pix], bank 8q+r; reused as y_s

    int sel = blockIdx.y;
    const float *w, *pb, *ps, *pt, *pm, *pv;
    int oc0;
    if (sel == 0)      { w = w1; pb = b1; ps = s1; pt = t1; pm = m1; pv = v1; oc0 = 0; }
    else if (sel == 1) { w = w2; pb = b2; ps = s2; pt = t2; pm = m2; pv = v2; oc0 = 0; }
    else               { w = w3; pb = b3; ps = s3; pt = t3; pm = m3; pv = v3; oc0 = (sel - 2) * 32; }

    int b  = blockIdx.z;
    int p0 = blockIdx.x * 256;
    int tid = threadIdx.x, lane = tid & 31, warp = tid >> 5;
    int q = lane & 3, r = lane >> 2;

    const float* xb = x + (size_t)b * CC * HW + p0;

    float acc[2][4][4];
#pragma unroll
    for (int mt = 0; mt < 2; mt++)
#pragma unroll
        for (int nc = 0; nc < 4; nc++)
#pragma unroll
            for (int i = 0; i < 4; i++) acc[mt][nc][i] = 0.f;

    for (int kc0 = 0; kc0 < CC; kc0 += 32) {
        {
            int oc = tid >> 3, kg = tid & 7;
            *(uint4*)&w_s[oc * 36 + kg * 4] =
                *(const uint4*)&w[(size_t)(oc0 + oc) * CC + kc0 + kg * 4];
        }
#pragma unroll
        for (int j = 0; j < 8; j++) {
            int e = tid + 256 * j;
            int k = e >> 6, p4 = e & 63;
            *(uint4*)&x_s[k * 264 + p4 * 4] =
                *(const uint4*)&xb[(size_t)(kc0 + k) * HW + p4 * 4];
        }
        __syncthreads();

        int nbase = warp * 32 + r;
#pragma unroll
        for (int kc = 0; kc < 4; kc++) {
            uint32_t a[2][4];
#pragma unroll
            for (int mt = 0; mt < 2; mt++) {
                a[mt][0] = w_s[(mt * 16 + r) * 36 + kc * 8 + q];
                a[mt][1] = w_s[(mt * 16 + r + 8) * 36 + kc * 8 + q];
                a[mt][2] = w_s[(mt * 16 + r) * 36 + kc * 8 + q + 4];
                a[mt][3] = w_s[(mt * 16 + r + 8) * 36 + kc * 8 + q + 4];
            }
#pragma unroll
            for (int nc = 0; nc < 4; nc++) {
                uint32_t bb0 = x_s[(kc * 8 + q) * 264 + nbase + nc * 8];
                uint32_t bb1 = x_s[(kc * 8 + q + 4) * 264 + nbase + nc * 8];
                mma_tf32(acc[0][nc], a[0], bb0, bb1);
                mma_tf32(acc[1][nc], a[1], bb0, bb1);
            }
        }
        __syncthreads();
    }

    // ---- epilogue: BN(+ReLU) into smem staging (reuse x_s), then write out
    float* y_s = (float*)x_s;
    float gsc[2][2], gsh[2][2];
#pragma unroll
    for (int mt = 0; mt < 2; mt++)
#pragma unroll
        for (int h2 = 0; h2 < 2; h2++) {
            int oc = oc0 + mt * 16 + r + 8 * h2;
            float sc = ps[oc] * rsqrtf(pv[oc] + EPSV);
            gsc[mt][h2] = sc;
            gsh[mt][h2] = (pb[oc] - pm[oc]) * sc + pt[oc];
        }
#pragma unroll
    for (int mt = 0; mt < 2; mt++)
#pragma unroll
        for (int nc = 0; nc < 4; nc++) {
            int col = warp * 32 + nc * 8 + 2 * q;
            float2 v0 = make_float2(
                fmaxf(acc[mt][nc][0] * gsc[mt][0] + gsh[mt][0], 0.f),
                fmaxf(acc[mt][nc][1] * gsc[mt][0] + gsh[mt][0], 0.f));
            float2 v1 = make_float2(
                fmaxf(acc[mt][nc][2] * gsc[mt][1] + gsh[mt][1], 0.f),
                fmaxf(acc[mt][nc][3] * gsc[mt][1] + gsh[mt][1], 0.f));
            *(float2*)&y_s[(mt * 16 + r) * 264 + col]     = v0;
            *(float2*)&y_s[(mt * 16 + r + 8) * 264 + col] = v1;
        }
    __syncthreads();

    if (sel == 1) {
        float* op = g_g + (size_t)b * 32 * HW + p0;
#pragma unroll
        for (int j = 0; j < 32; j++) {
            int e = tid + 256 * j;
            int oc = e >> 8, pix = e & 255;
            op[(size_t)oc * HW + pix] = y_s[oc * 264 + pix];
        }
        return;
    }

    // pooled writes in flash fragment order.
    int PR0 = p0 >> 7;   // tile index base (2 pooled rows = 2 n-tiles per CTA)
    if (sel == 0) {
        float* outp = g_f + (size_t)b * 32768;
#pragma unroll
        for (int j = 0; j < 8; j++) {
            int e = tid + 256 * j;        // < 2048
            int ocl = e >> 6, qq = e & 63;
            int pq = qq >> 5, col = qq & 31;
            int base = ocl * 264 + pq * 128 + 2 * col;
            float v01 = fmaxf(y_s[base],      y_s[base + 1]);
            float v23 = fmaxf(y_s[base + 64], y_s[base + 65]);
            float v = fmaxf(v01, v23);
            // fB frag addr: k=ocl, n5=col
            int addr = (PR0 + pq) * 1024 + (col >> 3) * 256 + (ocl >> 4) * 128
                     + ((col & 7) * 4 + (ocl & 3)) * 4 + ((ocl >> 2) & 3);
            outp[addr] = v;
        }
    } else {
        float* outp = g_hh + (size_t)b * 131072;
#pragma unroll
        for (int j = 0; j < 8; j++) {
            int e = tid + 256 * j;
            int ocl = e >> 6, qq = e & 63;
            int pq = qq >> 5, col = qq & 31;
            int base = ocl * 264 + pq * 128 + 2 * col;
            float v01 = fmaxf(y_s[base],      y_s[base + 1]);
            float v23 = fmaxf(y_s[base + 64], y_s[base + 65]);
            float v = fmaxf(v01, v23);
            // hB frag addr: c=oc0+ocl, n5=col
            int c = oc0 + ocl;
            int addr = (PR0 + pq) * 4096 + (c >> 3) * 256 + (col >> 4) * 128
                     + ((c & 7) * 4 + (col & 3)) * 4 + ((col >> 2) & 3);
            outp[addr] = v;
        }
    }
}

// ---------------------------------------------------------------------------
// Kernel 2: flash attention on tensor cores. B operands arrive in fragment
// order from gmem -> fills are pure coalesced uint4 copies. Rescale skipped
// when the running max didn't change (fac == 1 exactly).
// ---------------------------------------------------------------------------
__global__ __launch_bounds__(256) void flash_mma_kernel()
{
    __shared__ __align__(16) uint32_t fB[4][2][32][4];    //  4 KB (QK B: f)
    __shared__ __align__(16) uint32_t hB[16][2][32][4];   // 16 KB (PV B: hh)
    __shared__ __align__(16) uint32_t pS[8][16][36];      // 18 KB warp-private p

    int b = blockIdx.y, m0 = blockIdx.x * 128;
    int tid  = threadIdx.x;
    int lane = tid & 31, warp = tid >> 5;
    int q = lane & 3, r = lane >> 2;

    const float* gb = g_g + (size_t)b * 32 * HW + m0 + warp * 16;

    uint32_t gA[4][4];
#pragma unroll
    for (int kc = 0; kc < 4; kc++) {
        gA[kc][0] = __float_as_uint(gb[(size_t)(kc * 8 + q)     * HW + r]);
        gA[kc][1] = __float_as_uint(gb[(size_t)(kc * 8 + q)     * HW + r + 8]);
        gA[kc][2] = __float_as_uint(gb[(size_t)(kc * 8 + q + 4) * HW + r]);
        gA[kc][3] = __float_as_uint(gb[(size_t)(kc * 8 + q + 4) * HW + r + 8]);
    }

    float mx0 = -INFINITY, mx1 = -INFINITY, l0 = 0.f, l1 = 0.f;
    float acc[16][4];
#pragma unroll
    for (int cc = 0; cc < 16; cc++)
#pragma unroll
        for (int i = 0; i < 4; i++) acc[cc][i] = 0.f;

    const uint4* fsrc = (const uint4*)(g_f  + (size_t)b * 32768);
    const uint4* hsrc = (const uint4*)(g_hh + (size_t)b * 131072);

    for (int nt = 0; nt < 32; nt++) {
        // ---- fills: pure coalesced copies (fragment order in gmem)
        ((uint4*)fB)[tid] = fsrc[nt * 256 + tid];
#pragma unroll
        for (int j = 0; j < 4; j++)
            ((uint4*)hB)[tid + 256 * j] = hsrc[nt * 1024 + tid + 256 * j];
        __syncthreads();

        // ---- QK: sT[16m x 32n] per warp
        float s[4][4];
#pragma unroll
        for (int nc = 0; nc < 4; nc++)
#pragma unroll
            for (int i = 0; i < 4; i++) s[nc][i] = 0.f;
#pragma unroll
        for (int nc = 0; nc < 4; nc++) {
            uint4 f0 = *(const uint4*)fB[nc][0][lane];
            uint4 f1 = *(const uint4*)fB[nc][1][lane];
            mma_tf32(s[nc], gA[0], f0.x, f0.y);
            mma_tf32(s[nc], gA[1], f0.z, f0.w);
            mma_tf32(s[nc], gA[2], f1.x, f1.y);
            mma_tf32(s[nc], gA[3], f1.z, f1.w);
        }

        // ---- row max (rows r, r+8), quad reduction
        float t0 = fmaxf(fmaxf(s[0][0], s[0][1]), fmaxf(s[1][0], s[1][1]));
        t0 = fmaxf(t0, fmaxf(fmaxf(s[2][0], s[2][1]), fmaxf(s[3][0], s[3][1])));
        float t1 = fmaxf(fmaxf(s[0][2], s[0][3]), fmaxf(s[1][2], s[1][3]));
        t1 = fmaxf(t1, fmaxf(fmaxf(s[2][2], s[2][3]), fmaxf(s[3][2], s[3][3])));
        t0 = fmaxf(t0, __shfl_xor_sync(0xffffffffu, t0, 1));
        t0 = fmaxf(t0, __shfl_xor_sync(0xffffffffu, t0, 2));
        t1 = fmaxf(t1, __shfl_xor_sync(0xffffffffu, t1, 1));
        t1 = fmaxf(t1, __shfl_xor_sync(0xffffffffu, t1, 2));
        float nm0 = fmaxf(mx0, t0), nm1 = fmaxf(mx1, t1);
        float fac0 = __expf(mx0 - nm0), fac1 = __expf(mx1 - nm1);
        mx0 = nm0; mx1 = nm1;

        // ---- exp + p store + partial row sums
        float ps0 = 0.f, ps1 = 0.f;
#pragma unroll
        for (int nc = 0; nc < 4; nc++) {
            float e0 = __expf(s[nc][0] - mx0);
            float e1 = __expf(s[nc][1] - mx0);
            float e2 = __expf(s[nc][2] - mx1);
            float e3 = __expf(s[nc][3] - mx1);
            ps0 += e0 + e1; ps1 += e2 + e3;
            *(uint2*)&pS[warp][r]    [nc * 8 + 2 * q] =
                make_uint2(__float_as_uint(e0), __float_as_uint(e1));
            *(uint2*)&pS[warp][r + 8][nc * 8 + 2 * q] =
                make_uint2(__float_as_uint(e2), __float_as_uint(e3));
        }
        ps0 += __shfl_xor_sync(0xffffffffu, ps0, 1);
        ps0 += __shfl_xor_sync(0xffffffffu, ps0, 2);
        ps1 += __shfl_xor_sync(0xffffffffu, ps1, 1);
        ps1 += __shfl_xor_sync(0xffffffffu, ps1, 2);
        l0 = l0 * fac0 + ps0;
        l1 = l1 * fac1 + ps1;

        // ---- rescale accumulator only if some row max changed (fac != 1)
        bool need = (fac0 != 1.f) || (fac1 != 1.f);
        if (__any_sync(0xffffffffu, need)) {
#pragma unroll
            for (int cc = 0; cc < 16; cc++) {
                acc[cc][0] *= fac0; acc[cc][1] *= fac0;
                acc[cc][2] *= fac1; acc[cc][3] *= fac1;
            }
        }

        __syncwarp();
        uint32_t pA[4][4];
#pragma unroll
        for (int kc = 0; kc < 4; kc++) {
            pA[kc][0] = pS[warp][r]    [kc * 8 + q];
            pA[kc][1] = pS[warp][r + 8][kc * 8 + q];
            pA[kc][2] = pS[warp][r]    [kc * 8 + q + 4];
            pA[kc][3] = pS[warp][r + 8][kc * 8 + q + 4];
        }

        // ---- PV: oT[16m x 128c] += p[16m x 32n] * hhT[32n x 128c]
#pragma unroll
        for (int cc = 0; cc < 16; cc++) {
            uint4 h0 = *(const uint4*)hB[cc][0][lane];
            uint4 h1 = *(const uint4*)hB[cc][1][lane];
            mma_tf32(acc[cc], pA[0], h0.x, h0.y);
            mma_tf32(acc[cc], pA[1], h0.z, h0.w);
            mma_tf32(acc[cc], pA[2], h1.x, h1.y);
            mma_tf32(acc[cc], pA[3], h1.z, h1.w);
        }
        __syncthreads();
    }

    float rl0 = 1.f / l0, rl1 = 1.f / l1;
    float* ot = g_oT + ((size_t)b * HW + m0 + warp * 16) * 128;
#pragma unroll
    for (int cc = 0; cc < 16; cc++) {
        int c = cc * 8 + 2 * q;
        *(float2*)&ot[(size_t)r * 128 + c] =
            make_float2(acc[cc][0] * rl0, acc[cc][1] * rl0);
        *(float2*)&ot[(size_t)(r + 8) * 128 + c] =
            make_float2(acc[cc][2] * rl1, acc[cc][3] * rl1);
    }
}

// ---------------------------------------------------------------------------
// Kernel 3: out = gamma * BN(conv4(o)) + x, on tensor cores.
// grid (64 pixtiles, 2 octiles, 8 b), 256 thr = 8 warps.
// CTA: 128 oc x 64 pix, K=128. Raw staging, stride-36 conflict-free frags.
// ---------------------------------------------------------------------------
__global__ __launch_bounds__(256) void conv4_mma_kernel(
    const float* __restrict__ x,
    const float* __restrict__ w4, const float* __restrict__ b4, const float* __restrict__ s4,
    const float* __restrict__ t4, const float* __restrict__ m4, const float* __restrict__ v4,
    const float* __restrict__ gamma, float* __restrict__ out)
{
    __shared__ __align__(16) uint32_t w4_s[128 * 36];   // [oc][k] raw bits
    __shared__ __align__(16) uint32_t o_s [64 * 36];    // [pix][k] raw bits

    int b = blockIdx.z, oc0 = blockIdx.y * 128, p0 = blockIdx.x * 64;
    int tid = threadIdx.x, lane = tid & 31, warp = tid >> 5;
    int q = lane & 3, r = lane >> 2;

    const float* obT = g_oT + (size_t)b * HW * 128 + (size_t)p0 * 128;

    float acc[8][4];
#pragma unroll
    for (int nc = 0; nc < 8; nc++)
#pragma unroll
        for (int i = 0; i < 4; i++) acc[nc][i] = 0.f;

    for (int kc0 = 0; kc0 < 128; kc0 += 32) {
#pragma unroll
        for (int j = 0; j < 4; j++) {
            int e = tid + 256 * j;
            int oc = e >> 3, kg = e & 7;
            *(uint4*)&w4_s[oc * 36 + kg * 4] =
                *(const uint4*)&w4[(size_t)(oc0 + oc) * 128 + kc0 + kg * 4];
        }
#pragma unroll
        for (int j = 0; j < 2; j++) {
            int e = tid + 256 * j;
            int n = e >> 3, kg = e & 7;
            *(uint4*)&o_s[n * 36 + kg * 4] =
                *(const uint4*)&obT[(size_t)n * 128 + kc0 + kg * 4];
        }
        __syncthreads();

#pragma unroll
        for (int kc = 0; kc < 4; kc++) {
            uint32_t a[4];
            a[0] = w4_s[(warp * 16 + r) * 36 + kc * 8 + q];
            a[1] = w4_s[(warp * 16 + r + 8) * 36 + kc * 8 + q];
            a[2] = w4_s[(warp * 16 + r) * 36 + kc * 8 + q + 4];
            a[3] = w4_s[(warp * 16 + r + 8) * 36 + kc * 8 + q + 4];
#pragma unroll
            for (int nc = 0; nc < 8; nc++) {
                uint32_t bb0 = o_s[(nc * 8 + r) * 36 + kc * 8 + q];
                uint32_t bb1 = o_s[(nc * 8 + r) * 36 + kc * 8 + q + 4];
                mma_tf32(acc[nc], a, bb0, bb1);
            }
        }
        __syncthreads();
    }

    float gm = *gamma;
    int ocA = oc0 + warp * 16 + r, ocB = ocA + 8;
    float scA = s4[ocA] * rsqrtf(v4[ocA] + EPSV);
    float shA = (b4[ocA] - m4[ocA]) * scA + t4[ocA];
    float scB = s4[ocB] * rsqrtf(v4[ocB] + EPSV);
    float shB = (b4[ocB] - m4[ocB]) * scB + t4[ocB];
    const float* xpA = x   + ((size_t)b * CC + ocA) * HW + p0;
    float*       opA = out + ((size_t)b * CC + ocA) * HW + p0;
    const float* xpB = xpA + 8 * HW;
    float*       opB = opA + 8 * HW;
#pragma unroll
    for (int nc = 0; nc < 8; nc++) {
        int pix = nc * 8 + 2 * q;
        *(float2*)&opA[pix] = make_float2(
            gm * (acc[nc][0] * scA + shA) + xpA[pix],
            gm * (acc[nc][1] * scA + shA) + xpA[pix + 1]);
        *(float2*)&opB[pix] = make_float2(
            gm * (acc[nc][2] * scB + shB) + xpB[pix],
            gm * (acc[nc][3] * scB + shB) + xpB[pix + 1]);
    }
}

// ---------------------------------------------------------------------------
extern "C" void kernel_launch(void* const* d_in, const int* in_sizes, int n_in,
                              void* d_out, int out_size)
{
    (void)in_sizes; (void)n_in; (void)out_size;
    const float* x = (const float*)d_in[0];
#define P(i) ((const float*)d_in[i])

    conv123_mma_kernel<<<dim3(16, 6, 8), 256>>>(
        x,
        P(1), P(2), P(3), P(4), P(5), P(6),        // conv1
        P(7), P(8), P(9), P(10), P(11), P(12),     // conv2
        P(13), P(14), P(15), P(16), P(17), P(18)); // conv3

    flash_mma_kernel<<<dim3(32, 8), 256>>>();

    conv4_mma_kernel<<<dim3(64, 2, 8), 256>>>(
        x, P(19), P(20), P(21), P(22), P(23), P(24), P(25), (float*)d_out);
#undef P
}

// round 12
// speedup vs baseline: 1.9814x; 1.1545x over previous
#include <cuda_runtime.h>
#include <math.h>
#include <stdint.h>

// Problem constants
#define BB   8
#define CC   256
#define HW   4096
#define HW4  1024
#define EPSV 1e-5f

// D(16x8,f32) += A(16x8,tf32) * B(8x8,tf32)
// Operands carry raw fp32 bits; HW uses the 19 tf32 bits (truncation).
__device__ __forceinline__ void mma_tf32(float* c, const uint32_t* a, uint32_t b0, uint32_t b1) {
    asm volatile(
        "mma.sync.aligned.m16n8k8.row.col.f32.tf32.tf32.f32 "
        "{%0,%1,%2,%3}, {%4,%5,%6,%7}, {%8,%9}, {%0,%1,%2,%3};"
        : "+f"(c[0]), "+f"(c[1]), "+f"(c[2]), "+f"(c[3])
        : "r"(a[0]), "r"(a[1]), "r"(a[2]), "r"(a[3]), "r"(b0), "r"(b1));
}

// ---- cp.async helpers ----
__device__ __forceinline__ void cp16(uint32_t smem_dst, const void* gmem_src) {
    asm volatile("cp.async.cg.shared.global [%0], [%1], 16;"
                 :: "r"(smem_dst), "l"(gmem_src));
}
#define CP_COMMIT()  asm volatile("cp.async.commit_group;" ::: "memory")
#define CP_WAIT1()   asm volatile("cp.async.wait_group 1;" ::: "memory")
#define CP_WAIT0()   asm volatile("cp.async.wait_group 0;" ::: "memory")

// ---------------- scratch (static __device__ — allocation-free) ----------------
// g_f / g_hh are stored in flash's B-fragment order:
//   g_f : per b, 32 n-tiles of [nc=4][ch=2][ln=32][t_=4]  (1024 words/tile)
//   g_hh: per b, 32 n-tiles of [cc=16][ch=2][ln=32][t_=4] (4096 words/tile)
__device__ float g_g  [BB * 32 * HW];          //  4 MB  conv2 (g)  [b][k][m]
__device__ float g_f  [BB * 32 * HW4];         //  1 MB  pooled f   (frag order)
__device__ float g_hh [BB * 128 * HW4];        //  4 MB  pooled hh  (frag order)
__device__ float g_oT [(size_t)BB * HW * 128]; // 16 MB  oT         [b][m][c]

// ---------------------------------------------------------------------------
// Kernel 1: fused conv1/conv2/conv3 (1x1 conv + BN + ReLU) on tensor cores,
// cp.async double-buffered. grid (16 pixtiles, 6 sel, 8 b), 256 thr.
// CTA tile: 32 oc x 256 pix, K=256 in chunks of 32.
// Dynamic smem: w[2][32*36] + x[2][32*264] = 76.8 KB.
// ---------------------------------------------------------------------------
#define C1_WSTR 1152    // 32*36
#define C1_XSTR 8448    // 32*264
#define C1_XOFF 2304    // 2*C1_WSTR
#define C1_WORDS (C1_XOFF + 2 * C1_XSTR)

__global__ __launch_bounds__(256) void conv123_mma_kernel(
    const float* __restrict__ x,
    const float* __restrict__ w1, const float* __restrict__ b1, const float* __restrict__ s1,
    const float* __restrict__ t1, const float* __restrict__ m1, const float* __restrict__ v1,
    const float* __restrict__ w2, const float* __restrict__ b2, const float* __restrict__ s2,
    const float* __restrict__ t2, const float* __restrict__ m2, const float* __restrict__ v2,
    const float* __restrict__ w3, const float* __restrict__ b3, const float* __restrict__ s3,
    const float* __restrict__ t3, const float* __restrict__ m3, const float* __restrict__ v3)
{
    extern __shared__ __align__(16) uint32_t dyn[];
    uint32_t* w_s = dyn;              // [2][C1_WSTR]
    uint32_t* x_s = dyn + C1_XOFF;    // [2][C1_XSTR]
    uint32_t smem0 = (uint32_t)__cvta_generic_to_shared(dyn);

    int sel = blockIdx.y;
    const float *w, *pb, *ps, *pt, *pm, *pv;
    int oc0;
    if (sel == 0)      { w = w1; pb = b1; ps = s1; pt = t1; pm = m1; pv = v1; oc0 = 0; }
    else if (sel == 1) { w = w2; pb = b2; ps = s2; pt = t2; pm = m2; pv = v2; oc0 = 0; }
    else               { w = w3; pb = b3; ps = s3; pt = t3; pm = m3; pv = v3; oc0 = (sel - 2) * 32; }

    int b  = blockIdx.z;
    int p0 = blockIdx.x * 256;
    int tid = threadIdx.x, lane = tid & 31, warp = tid >> 5;
    int q = lane & 3, r = lane >> 2;

    const float* xb = x + (size_t)b * CC * HW + p0;

    // staging indices (constant per thread)
    int wsoc = tid >> 3, wskg = tid & 7;
    uint32_t wdst = smem0 + ((uint32_t)(wsoc * 36 + wskg * 4) << 2);
    const float* wsrc0 = w + (size_t)(oc0 + wsoc) * CC + wskg * 4;

    float acc[2][4][4];
#pragma unroll
    for (int mt = 0; mt < 2; mt++)
#pragma unroll
        for (int nc = 0; nc < 4; nc++)
#pragma unroll
            for (int i = 0; i < 4; i++) acc[mt][nc][i] = 0.f;

    // ---- prologue: stage chunk 0 into buf 0
    {
        cp16(wdst, wsrc0);
#pragma unroll
        for (int j = 0; j < 8; j++) {
            int e = tid + 256 * j;
            int k = e >> 6, p4 = e & 63;
            cp16(smem0 + ((uint32_t)(C1_XOFF + k * 264 + p4 * 4) << 2),
                 &xb[(size_t)k * HW + p4 * 4]);
        }
        CP_COMMIT();
    }

    int buf = 0;
    for (int c = 0; c < 8; c++) {
        if (c < 7) {   // stage chunk c+1 into buf^1
            int nb = buf ^ 1;
            cp16(wdst + ((uint32_t)(nb * C1_WSTR) << 2), wsrc0 + (c + 1) * 32);
#pragma unroll
            for (int j = 0; j < 8; j++) {
                int e = tid + 256 * j;
                int k = e >> 6, p4 = e & 63;
                cp16(smem0 + ((uint32_t)(C1_XOFF + nb * C1_XSTR + k * 264 + p4 * 4) << 2),
                     &xb[(size_t)((c + 1) * 32 + k) * HW + p4 * 4]);
            }
            CP_COMMIT();
            CP_WAIT1();
        } else {
            CP_WAIT0();
        }
        __syncthreads();

        const uint32_t* wb = w_s + buf * C1_WSTR;
        const uint32_t* xbuf = x_s + buf * C1_XSTR;
        int nbase = warp * 32 + r;
#pragma unroll
        for (int kc = 0; kc < 4; kc++) {
            uint32_t a[2][4];
#pragma unroll
            for (int mt = 0; mt < 2; mt++) {
                a[mt][0] = wb[(mt * 16 + r) * 36 + kc * 8 + q];
                a[mt][1] = wb[(mt * 16 + r + 8) * 36 + kc * 8 + q];
                a[mt][2] = wb[(mt * 16 + r) * 36 + kc * 8 + q + 4];
                a[mt][3] = wb[(mt * 16 + r + 8) * 36 + kc * 8 + q + 4];
            }
#pragma unroll
            for (int nc = 0; nc < 4; nc++) {
                uint32_t bb0 = xbuf[(kc * 8 + q) * 264 + nbase + nc * 8];
                uint32_t bb1 = xbuf[(kc * 8 + q + 4) * 264 + nbase + nc * 8];
                mma_tf32(acc[0][nc], a[0], bb0, bb1);
                mma_tf32(acc[1][nc], a[1], bb0, bb1);
            }
        }
        __syncthreads();
        buf ^= 1;
    }

    // ---- epilogue: BN(+ReLU) into smem staging (x buffer 0), then write out
    float* y_s = (float*)(dyn + C1_XOFF);
    float gsc[2][2], gsh[2][2];
#pragma unroll
    for (int mt = 0; mt < 2; mt++)
#pragma unroll
        for (int h2 = 0; h2 < 2; h2++) {
            int oc = oc0 + mt * 16 + r + 8 * h2;
            float sc = ps[oc] * rsqrtf(pv[oc] + EPSV);
            gsc[mt][h2] = sc;
            gsh[mt][h2] = (pb[oc] - pm[oc]) * sc + pt[oc];
        }
#pragma unroll
    for (int mt = 0; mt < 2; mt++)
#pragma unroll
        for (int nc = 0; nc < 4; nc++) {
            int col = warp * 32 + nc * 8 + 2 * q;
            float2 v0 = make_float2(
                fmaxf(acc[mt][nc][0] * gsc[mt][0] + gsh[mt][0], 0.f),
                fmaxf(acc[mt][nc][1] * gsc[mt][0] + gsh[mt][0], 0.f));
            float2 v1 = make_float2(
                fmaxf(acc[mt][nc][2] * gsc[mt][1] + gsh[mt][1], 0.f),
                fmaxf(acc[mt][nc][3] * gsc[mt][1] + gsh[mt][1], 0.f));
            *(float2*)&y_s[(mt * 16 + r) * 264 + col]     = v0;
            *(float2*)&y_s[(mt * 16 + r + 8) * 264 + col] = v1;
        }
    __syncthreads();

    if (sel == 1) {
        float* op = g_g + (size_t)b * 32 * HW + p0;
#pragma unroll
        for (int j = 0; j < 32; j++) {
            int e = tid + 256 * j;
            int oc = e >> 8, pix = e & 255;
            op[(size_t)oc * HW + pix] = y_s[oc * 264 + pix];
        }
        return;
    }

    // pooled writes in flash fragment order.
    int PR0 = p0 >> 7;
    if (sel == 0) {
        float* outp = g_f + (size_t)b * 32768;
#pragma unroll
        for (int j = 0; j < 8; j++) {
            int e = tid + 256 * j;
            int ocl = e >> 6, qq = e & 63;
            int pq = qq >> 5, col = qq & 31;
            int base = ocl * 264 + pq * 128 + 2 * col;
            float v01 = fmaxf(y_s[base],      y_s[base + 1]);
            float v23 = fmaxf(y_s[base + 64], y_s[base + 65]);
            float v = fmaxf(v01, v23);
            int addr = (PR0 + pq) * 1024 + (col >> 3) * 256 + (ocl >> 4) * 128
                     + ((col & 7) * 4 + (ocl & 3)) * 4 + ((ocl >> 2) & 3);
            outp[addr] = v;
        }
    } else {
        float* outp = g_hh + (size_t)b * 131072;
#pragma unroll
        for (int j = 0; j < 8; j++) {
            int e = tid + 256 * j;
            int ocl = e >> 6, qq = e & 63;
            int pq = qq >> 5, col = qq & 31;
            int base = ocl * 264 + pq * 128 + 2 * col;
            float v01 = fmaxf(y_s[base],      y_s[base + 1]);
            float v23 = fmaxf(y_s[base + 64], y_s[base + 65]);
            float v = fmaxf(v01, v23);
            int c = oc0 + ocl;
            int addr = (PR0 + pq) * 4096 + (c >> 3) * 256 + (col >> 4) * 128
                     + ((c & 7) * 4 + (col & 3)) * 4 + ((col >> 2) & 3);
            outp[addr] = v;
        }
    }
}

// ---------------------------------------------------------------------------
// Kernel 2: flash attention on tensor cores, cp.async double-buffered fills.
// Dynamic smem: fB[2][1024] + hB[2][4096] + pS[4608] = 59.4 KB.
// ---------------------------------------------------------------------------
#define FL_FB    0
#define FL_HB    2048
#define FL_PS    10240
#define FL_WORDS 14848

__global__ __launch_bounds__(256) void flash_mma_kernel()
{
    extern __shared__ __align__(16) uint32_t dyn[];
    uint32_t smem0 = (uint32_t)__cvta_generic_to_shared(dyn);
    uint32_t* pS = dyn + FL_PS;   // [8][16][36]

    int b = blockIdx.y, m0 = blockIdx.x * 128;
    int tid  = threadIdx.x;
    int lane = tid & 31, warp = tid >> 5;
    int q = lane & 3, r = lane >> 2;

    const uint4* fsrc = (const uint4*)(g_f  + (size_t)b * 32768);
    const uint4* hsrc = (const uint4*)(g_hh + (size_t)b * 131072);

    // ---- prologue: stage tile 0 into buf 0
    {
        cp16(smem0 + ((uint32_t)(FL_FB + tid * 4) << 2), &fsrc[tid]);
#pragma unroll
        for (int j = 0; j < 4; j++)
            cp16(smem0 + ((uint32_t)(FL_HB + (tid + 256 * j) * 4) << 2),
                 &hsrc[tid + 256 * j]);
        CP_COMMIT();
    }

    const float* gb = g_g + (size_t)b * 32 * HW + m0 + warp * 16;
    uint32_t gA[4][4];
#pragma unroll
    for (int kc = 0; kc < 4; kc++) {
        gA[kc][0] = __float_as_uint(gb[(size_t)(kc * 8 + q)     * HW + r]);
        gA[kc][1] = __float_as_uint(gb[(size_t)(kc * 8 + q)     * HW + r + 8]);
        gA[kc][2] = __float_as_uint(gb[(size_t)(kc * 8 + q + 4) * HW + r]);
        gA[kc][3] = __float_as_uint(gb[(size_t)(kc * 8 + q + 4) * HW + r + 8]);
    }

    float mx0 = -INFINITY, mx1 = -INFINITY, l0 = 0.f, l1 = 0.f;
    float acc[16][4];
#pragma unroll
    for (int cc = 0; cc < 16; cc++)
#pragma unroll
        for (int i = 0; i < 4; i++) acc[cc][i] = 0.f;

    int buf = 0;
    for (int nt = 0; nt < 32; nt++) {
        if (nt < 31) {   // stage tile nt+1 into buf^1
            int nb = buf ^ 1;
            cp16(smem0 + ((uint32_t)(FL_FB + nb * 1024 + tid * 4) << 2),
                 &fsrc[(nt + 1) * 256 + tid]);
#pragma unroll
            for (int j = 0; j < 4; j++)
                cp16(smem0 + ((uint32_t)(FL_HB + nb * 4096 + (tid + 256 * j) * 4) << 2),
                     &hsrc[(nt + 1) * 1024 + tid + 256 * j]);
            CP_COMMIT();
            CP_WAIT1();
        } else {
            CP_WAIT0();
        }
        __syncthreads();

        const uint32_t* fBb = dyn + FL_FB + buf * 1024;
        const uint32_t* hBb = dyn + FL_HB + buf * 4096;

        // ---- QK: sT[16m x 32n] per warp
        float s[4][4];
#pragma unroll
        for (int nc = 0; nc < 4; nc++)
#pragma unroll
            for (int i = 0; i < 4; i++) s[nc][i] = 0.f;
#pragma unroll
        for (int nc = 0; nc < 4; nc++) {
            uint4 f0 = *(const uint4*)&fBb[(nc * 2 + 0) * 128 + lane * 4];
            uint4 f1 = *(const uint4*)&fBb[(nc * 2 + 1) * 128 + lane * 4];
            mma_tf32(s[nc], gA[0], f0.x, f0.y);
            mma_tf32(s[nc], gA[1], f0.z, f0.w);
            mma_tf32(s[nc], gA[2], f1.x, f1.y);
            mma_tf32(s[nc], gA[3], f1.z, f1.w);
        }

        // ---- row max (rows r, r+8), quad reduction
        float t0 = fmaxf(fmaxf(s[0][0], s[0][1]), fmaxf(s[1][0], s[1][1]));
        t0 = fmaxf(t0, fmaxf(fmaxf(s[2][0], s[2][1]), fmaxf(s[3][0], s[3][1])));
        float t1 = fmaxf(fmaxf(s[0][2], s[0][3]), fmaxf(s[1][2], s[1][3]));
        t1 = fmaxf(t1, fmaxf(fmaxf(s[2][2], s[2][3]), fmaxf(s[3][2], s[3][3])));
        t0 = fmaxf(t0, __shfl_xor_sync(0xffffffffu, t0, 1));
        t0 = fmaxf(t0, __shfl_xor_sync(0xffffffffu, t0, 2));
        t1 = fmaxf(t1, __shfl_xor_sync(0xffffffffu, t1, 1));
        t1 = fmaxf(t1, __shfl_xor_sync(0xffffffffu, t1, 2));
        float nm0 = fmaxf(mx0, t0), nm1 = fmaxf(mx1, t1);
        float fac0 = __expf(mx0 - nm0), fac1 = __expf(mx1 - nm1);
        mx0 = nm0; mx1 = nm1;

        // ---- exp + p store + partial row sums
        float ps0 = 0.f, ps1 = 0.f;
#pragma unroll
        for (int nc = 0; nc < 4; nc++) {
            float e0 = __expf(s[nc][0] - mx0);
            float e1 = __expf(s[nc][1] - mx0);
            float e2 = __expf(s[nc][2] - mx1);
            float e3 = __expf(s[nc][3] - mx1);
            ps0 += e0 + e1; ps1 += e2 + e3;
            *(uint2*)&pS[(warp * 16 + r) * 36 + nc * 8 + 2 * q] =
                make_uint2(__float_as_uint(e0), __float_as_uint(e1));
            *(uint2*)&pS[(warp * 16 + r + 8) * 36 + nc * 8 + 2 * q] =
                make_uint2(__float_as_uint(e2), __float_as_uint(e3));
        }
        ps0 += __shfl_xor_sync(0xffffffffu, ps0, 1);
        ps0 += __shfl_xor_sync(0xffffffffu, ps0, 2);
        ps1 += __shfl_xor_sync(0xffffffffu, ps1, 1);
        ps1 += __shfl_xor_sync(0xffffffffu, ps1, 2);
        l0 = l0 * fac0 + ps0;
        l1 = l1 * fac1 + ps1;

        // ---- rescale accumulator only if some row max changed (fac != 1)
        bool need = (fac0 != 1.f) || (fac1 != 1.f);
        if (__any_sync(0xffffffffu, need)) {
#pragma unroll
            for (int cc = 0; cc < 16; cc++) {
                acc[cc][0] *= fac0; acc[cc][1] *= fac0;
                acc[cc][2] *= fac1; acc[cc][3] *= fac1;
            }
        }

        __syncwarp();
        uint32_t pA[4][4];
#pragma unroll
        for (int kc = 0; kc < 4; kc++) {
            pA[kc][0] = pS[(warp * 16 + r) * 36 + kc * 8 + q];
            pA[kc][1] = pS[(warp * 16 + r + 8) * 36 + kc * 8 + q];
            pA[kc][2] = pS[(warp * 16 + r) * 36 + kc * 8 + q + 4];
            pA[kc][3] = pS[(warp * 16 + r + 8) * 36 + kc * 8 + q + 4];
        }

        // ---- PV: oT[16m x 128c] += p[16m x 32n] * hhT[32n x 128c]
#pragma unroll
        for (int cc = 0; cc < 16; cc++) {
            uint4 h0 = *(const uint4*)&hBb[(cc * 2 + 0) * 128 + lane * 4];
            uint4 h1 = *(const uint4*)&hBb[(cc * 2 + 1) * 128 + lane * 4];
            mma_tf32(acc[cc], pA[0], h0.x, h0.y);
            mma_tf32(acc[cc], pA[1], h0.z, h0.w);
            mma_tf32(acc[cc], pA[2], h1.x, h1.y);
            mma_tf32(acc[cc], pA[3], h1.z, h1.w);
        }
        __syncthreads();
        buf ^= 1;
    }

    float rl0 = 1.f / l0, rl1 = 1.f / l1;
    float* ot = g_oT + ((size_t)b * HW + m0 + warp * 16) * 128;
#pragma unroll
    for (int cc = 0; cc < 16; cc++) {
        int c = cc * 8 + 2 * q;
        *(float2*)&ot[(size_t)r * 128 + c] =
            make_float2(acc[cc][0] * rl0, acc[cc][1] * rl0);
        *(float2*)&ot[(size_t)(r + 8) * 128 + c] =
            make_float2(acc[cc][2] * rl1, acc[cc][3] * rl1);
    }
}

// ---------------------------------------------------------------------------
// Kernel 3: out = gamma * BN(conv4(o)) + x, cp.async double-buffered.
// grid (64 pixtiles, 2 octiles, 8 b). CTA: 128 oc x 64 pix, K=128.
// Dynamic smem: w4[2][4608] + o[2][2304] = 55.3 KB.
// ---------------------------------------------------------------------------
#define C4_WSTR 4608    // 128*36
#define C4_OSTR 2304    // 64*36
#define C4_OOFF 9216    // 2*C4_WSTR
#define C4_WORDS (C4_OOFF + 2 * C4_OSTR)

__global__ __launch_bounds__(256) void conv4_mma_kernel(
    const float* __restrict__ x,
    const float* __restrict__ w4, const float* __restrict__ b4, const float* __restrict__ s4,
    const float* __restrict__ t4, const float* __restrict__ m4, const float* __restrict__ v4,
    const float* __restrict__ gamma, float* __restrict__ out)
{
    extern __shared__ __align__(16) uint32_t dyn[];
    uint32_t* w4_s = dyn;              // [2][C4_WSTR]
    uint32_t* o_s  = dyn + C4_OOFF;    // [2][C4_OSTR]
    uint32_t smem0 = (uint32_t)__cvta_generic_to_shared(dyn);

    int b = blockIdx.z, oc0 = blockIdx.y * 128, p0 = blockIdx.x * 64;
    int tid = threadIdx.x, lane = tid & 31, warp = tid >> 5;
    int q = lane & 3, r = lane >> 2;

    const float* obT = g_oT + (size_t)b * HW * 128 + (size_t)p0 * 128;

    float acc[8][4];
#pragma unroll
    for (int nc = 0; nc < 8; nc++)
#pragma unroll
        for (int i = 0; i < 4; i++) acc[nc][i] = 0.f;

    // ---- prologue: stage chunk 0 into buf 0
    {
#pragma unroll
        for (int j = 0; j < 4; j++) {
            int e = tid + 256 * j;
            int oc = e >> 3, kg = e & 7;
            cp16(smem0 + ((uint32_t)(oc * 36 + kg * 4) << 2),
                 &w4[(size_t)(oc0 + oc) * 128 + kg * 4]);
        }
#pragma unroll
        for (int j = 0; j < 2; j++) {
            int e = tid + 256 * j;
            int n = e >> 3, kg = e & 7;
            cp16(smem0 + ((uint32_t)(C4_OOFF + n * 36 + kg * 4) << 2),
                 &obT[(size_t)n * 128 + kg * 4]);
        }
        CP_COMMIT();
    }

    int buf = 0;
    for (int c = 0; c < 4; c++) {
        if (c < 3) {
            int nb = buf ^ 1;
#pragma unroll
            for (int j = 0; j < 4; j++) {
                int e = tid + 256 * j;
                int oc = e >> 3, kg = e & 7;
                cp16(smem0 + ((uint32_t)(nb * C4_WSTR + oc * 36 + kg * 4) << 2),
                     &w4[(size_t)(oc0 + oc) * 128 + (c + 1) * 32 + kg * 4]);
            }
#pragma unroll
            for (int j = 0; j < 2; j++) {
                int e = tid + 256 * j;
                int n = e >> 3, kg = e & 7;
                cp16(smem0 + ((uint32_t)(C4_OOFF + nb * C4_OSTR + n * 36 + kg * 4) << 2),
                     &obT[(size_t)n * 128 + (c + 1) * 32 + kg * 4]);
            }
            CP_COMMIT();
            CP_WAIT1();
        } else {
            CP_WAIT0();
        }
        __syncthreads();

        const uint32_t* wb = w4_s + buf * C4_WSTR;
        const uint32_t* ob = o_s + buf * C4_OSTR;
#pragma unroll
        for (int kc = 0; kc < 4; kc++) {
            uint32_t a[4];
            a[0] = wb[(warp * 16 + r) * 36 + kc * 8 + q];
            a[1] = wb[(warp * 16 + r + 8) * 36 + kc * 8 + q];
            a[2] = wb[(warp * 16 + r) * 36 + kc * 8 + q + 4];
            a[3] = wb[(warp * 16 + r + 8) * 36 + kc * 8 + q + 4];
#pragma unroll
            for (int nc = 0; nc < 8; nc++) {
                uint32_t bb0 = ob[(nc * 8 + r) * 36 + kc * 8 + q];
                uint32_t bb1 = ob[(nc * 8 + r) * 36 + kc * 8 + q + 4];
                mma_tf32(acc[nc], a, bb0, bb1);
            }
        }
        __syncthreads();
        buf ^= 1;
    }

    float gm = *gamma;
    int ocA = oc0 + warp * 16 + r, ocB = ocA + 8;
    float scA = s4[ocA] * rsqrtf(v4[ocA] + EPSV);
    float shA = (b4[ocA] - m4[ocA]) * scA + t4[ocA];
    float scB = s4[ocB] * rsqrtf(v4[ocB] + EPSV);
    float shB = (b4[ocB] - m4[ocB]) * scB + t4[ocB];
    const float* xpA = x   + ((size_t)b * CC + ocA) * HW + p0;
    float*       opA = out + ((size_t)b * CC + ocA) * HW + p0;
    const float* xpB = xpA + 8 * HW;
    float*       opB = opA + 8 * HW;
#pragma unroll
    for (int nc = 0; nc < 8; nc++) {
        int pix = nc * 8 + 2 * q;
        *(float2*)&opA[pix] = make_float2(
            gm * (acc[nc][0] * scA + shA) + xpA[pix],
            gm * (acc[nc][1] * scA + shA) + xpA[pix + 1]);
        *(float2*)&opB[pix] = make_float2(
            gm * (acc[nc][2] * scB + shB) + xpB[pix],
            gm * (acc[nc][3] * scB + shB) + xpB[pix + 1]);
    }
}

// ---------------------------------------------------------------------------
extern "C" void kernel_launch(void* const* d_in, const int* in_sizes, int n_in,
                              void* d_out, int out_size)
{
    (void)in_sizes; (void)n_in; (void)out_size;
    const float* x = (const float*)d_in[0];
#define P(i) ((const float*)d_in[i])

    cudaFuncSetAttribute(conv123_mma_kernel, cudaFuncAttributeMaxDynamicSharedMemorySize,
                         C1_WORDS * 4);
    cudaFuncSetAttribute(flash_mma_kernel, cudaFuncAttributeMaxDynamicSharedMemorySize,
                         FL_WORDS * 4);
    cudaFuncSetAttribute(conv4_mma_kernel, cudaFuncAttributeMaxDynamicSharedMemorySize,
                         C4_WORDS * 4);

    conv123_mma_kernel<<<dim3(16, 6, 8), 256, C1_WORDS * 4>>>(
        x,
        P(1), P(2), P(3), P(4), P(5), P(6),        // conv1
        P(7), P(8), P(9), P(10), P(11), P(12),     // conv2
        P(13), P(14), P(15), P(16), P(17), P(18)); // conv3

    flash_mma_kernel<<<dim3(32, 8), 256, FL_WORDS * 4>>>();

    conv4_mma_kernel<<<dim3(64, 2, 8), 256, C4_WORDS * 4>>>(
        x, P(19), P(20), P(21), P(22), P(23), P(24), P(25), (float*)d_out);
#undef P
}

// round 16
// speedup vs baseline: 2.7483x; 1.3870x over previous
#include <cuda_runtime.h>
#include <cuda_bf16.h>
#include <math.h>
#include <stdint.h>

// Problem constants
#define BB   8
#define CC   256
#define HW   4096
#define HW4  1024
#define EPSV 1e-5f

// D(16x8,f32) += A(16x8,tf32) * B(8x8,tf32)  — raw fp32 bits (truncation)
__device__ __forceinline__ void mma_tf32(float* c, const uint32_t* a, uint32_t b0, uint32_t b1) {
    asm volatile(
        "mma.sync.aligned.m16n8k8.row.col.f32.tf32.tf32.f32 "
        "{%0,%1,%2,%3}, {%4,%5,%6,%7}, {%8,%9}, {%0,%1,%2,%3};"
        : "+f"(c[0]), "+f"(c[1]), "+f"(c[2]), "+f"(c[3])
        : "r"(a[0]), "r"(a[1]), "r"(a[2]), "r"(a[3]), "r"(b0), "r"(b1));
}

// D(16x8,f32) += A(16x16,bf16) * B(16x8,bf16)
__device__ __forceinline__ void mma_bf16(float* c, const uint32_t* a, uint32_t b0, uint32_t b1) {
    asm volatile(
        "mma.sync.aligned.m16n8k16.row.col.f32.bf16.bf16.f32 "
        "{%0,%1,%2,%3}, {%4,%5,%6,%7}, {%8,%9}, {%0,%1,%2,%3};"
        : "+f"(c[0]), "+f"(c[1]), "+f"(c[2]), "+f"(c[3])
        : "r"(a[0]), "r"(a[1]), "r"(a[2]), "r"(a[3]), "r"(b0), "r"(b1));
}

// pack two f32 -> bf16x2 {lo, hi}  (first asm source goes to the UPPER half)
__device__ __forceinline__ uint32_t pkbf(float lo, float hi) {
    uint32_t d;
    asm("cvt.rn.bf16x2.f32 %0, %1, %2;" : "=r"(d) : "f"(hi), "f"(lo));
    return d;
}

// ---- cp.async helpers ----
__device__ __forceinline__ void cp16(uint32_t smem_dst, const void* gmem_src) {
    asm volatile("cp.async.cg.shared.global [%0], [%1], 16;"
                 :: "r"(smem_dst), "l"(gmem_src));
}
#define CP_COMMIT()  asm volatile("cp.async.commit_group;" ::: "memory")
#define CP_WAIT1()   asm volatile("cp.async.wait_group 1;" ::: "memory")
#define CP_WAIT0()   asm volatile("cp.async.wait_group 0;" ::: "memory")

// ---------------- scratch (static __device__ — allocation-free) ----------------
// bf16 buffers, laid out for flash's m16n8k16 fragments:
//   g_g16 : [b][k/2=16][m=4096] u32 (k-pairs packed {lo=even k, hi=odd k})
//   g_f16 : per b, 32 n-tiles of [nc=4][kc=2][lane=32][t=2] u32  (512 u32/tile)
//   g_hh16: per b, 32 n-tiles of [cc=16][kc=2][lane=32][t=2] u32 (2048 u32/tile)
__device__ uint32_t g_g16 [BB * 16 * HW];      // 2 MB
__device__ uint32_t g_f16 [BB * 16384];        // 512 KB
__device__ uint32_t g_hh16[BB * 65536];        // 2 MB
__device__ float    g_oT  [(size_t)BB * HW * 128]; // 16 MB  oT [b][m][c] fp32

// ---------------------------------------------------------------------------
// Kernel 1: fused conv1/conv2/conv3 (1x1 conv + BN + ReLU) on tensor cores,
// cp.async double-buffered (mainloop identical to round 12).
// Epilogues emit bf16 in flash fragment order.
// ---------------------------------------------------------------------------
#define C1_WSTR 1152    // 32*36
#define C1_XSTR 8448    // 32*264
#define C1_XOFF 2304    // 2*C1_WSTR
#define C1_WORDS (C1_XOFF + 2 * C1_XSTR)

__global__ __launch_bounds__(256) void conv123_mma_kernel(
    const float* __restrict__ x,
    const float* __restrict__ w1, const float* __restrict__ b1, const float* __restrict__ s1,
    const float* __restrict__ t1, const float* __restrict__ m1, const float* __restrict__ v1,
    const float* __restrict__ w2, const float* __restrict__ b2, const float* __restrict__ s2,
    const float* __restrict__ t2, const float* __restrict__ m2, const float* __restrict__ v2,
    const float* __restrict__ w3, const float* __restrict__ b3, const float* __restrict__ s3,
    const float* __restrict__ t3, const float* __restrict__ m3, const float* __restrict__ v3)
{
    extern __shared__ __align__(16) uint32_t dyn[];
    uint32_t* w_s = dyn;              // [2][C1_WSTR]
    uint32_t* x_s = dyn + C1_XOFF;    // [2][C1_XSTR]
    uint32_t smem0 = (uint32_t)__cvta_generic_to_shared(dyn);

    int sel = blockIdx.y;
    const float *w, *pb, *ps, *pt, *pm, *pv;
    int oc0;
    if (sel == 0)      { w = w1; pb = b1; ps = s1; pt = t1; pm = m1; pv = v1; oc0 = 0; }
    else if (sel == 1) { w = w2; pb = b2; ps = s2; pt = t2; pm = m2; pv = v2; oc0 = 0; }
    else               { w = w3; pb = b3; ps = s3; pt = t3; pm = m3; pv = v3; oc0 = (sel - 2) * 32; }

    int b  = blockIdx.z;
    int p0 = blockIdx.x * 256;
    int tid = threadIdx.x, lane = tid & 31, warp = tid >> 5;
    int q = lane & 3, r = lane >> 2;

    const float* xb = x + (size_t)b * CC * HW + p0;

    int wsoc = tid >> 3, wskg = tid & 7;
    uint32_t wdst = smem0 + ((uint32_t)(wsoc * 36 + wskg * 4) << 2);
    const float* wsrc0 = w + (size_t)(oc0 + wsoc) * CC + wskg * 4;

    float acc[2][4][4];
#pragma unroll
    for (int mt = 0; mt < 2; mt++)
#pragma unroll
        for (int nc = 0; nc < 4; nc++)
#pragma unroll
            for (int i = 0; i < 4; i++) acc[mt][nc][i] = 0.f;

    {   // prologue
        cp16(wdst, wsrc0);
#pragma unroll
        for (int j = 0; j < 8; j++) {
            int e = tid + 256 * j;
            int k = e >> 6, p4 = e & 63;
            cp16(smem0 + ((uint32_t)(C1_XOFF + k * 264 + p4 * 4) << 2),
                 &xb[(size_t)k * HW + p4 * 4]);
        }
        CP_COMMIT();
    }

    int buf = 0;
    for (int c = 0; c < 8; c++) {
        if (c < 7) {
            int nb = buf ^ 1;
            cp16(wdst + ((uint32_t)(nb * C1_WSTR) << 2), wsrc0 + (c + 1) * 32);
#pragma unroll
            for (int j = 0; j < 8; j++) {
                int e = tid + 256 * j;
                int k = e >> 6, p4 = e & 63;
                cp16(smem0 + ((uint32_t)(C1_XOFF + nb * C1_XSTR + k * 264 + p4 * 4) << 2),
                     &xb[(size_t)((c + 1) * 32 + k) * HW + p4 * 4]);
            }
            CP_COMMIT();
            CP_WAIT1();
        } else {
            CP_WAIT0();
        }
        __syncthreads();

        const uint32_t* wb = w_s + buf * C1_WSTR;
        const uint32_t* xbuf = x_s + buf * C1_XSTR;
        int nbase = warp * 32 + r;
#pragma unroll
        for (int kc = 0; kc < 4; kc++) {
            uint32_t a[2][4];
#pragma unroll
            for (int mt = 0; mt < 2; mt++) {
                a[mt][0] = wb[(mt * 16 + r) * 36 + kc * 8 + q];
                a[mt][1] = wb[(mt * 16 + r + 8) * 36 + kc * 8 + q];
                a[mt][2] = wb[(mt * 16 + r) * 36 + kc * 8 + q + 4];
                a[mt][3] = wb[(mt * 16 + r + 8) * 36 + kc * 8 + q + 4];
            }
#pragma unroll
            for (int nc = 0; nc < 4; nc++) {
                uint32_t bb0 = xbuf[(kc * 8 + q) * 264 + nbase + nc * 8];
                uint32_t bb1 = xbuf[(kc * 8 + q + 4) * 264 + nbase + nc * 8];
                mma_tf32(acc[0][nc], a[0], bb0, bb1);
                mma_tf32(acc[1][nc], a[1], bb0, bb1);
            }
        }
        __syncthreads();
        buf ^= 1;
    }

    // ---- epilogue: BN(+ReLU) into smem staging, then bf16 writes
    float* y_s = (float*)(dyn + C1_XOFF);
    float gsc[2][2], gsh[2][2];
#pragma unroll
    for (int mt = 0; mt < 2; mt++)
#pragma unroll
        for (int h2 = 0; h2 < 2; h2++) {
            int oc = oc0 + mt * 16 + r + 8 * h2;
            float sc = ps[oc] * rsqrtf(pv[oc] + EPSV);
            gsc[mt][h2] = sc;
            gsh[mt][h2] = (pb[oc] - pm[oc]) * sc + pt[oc];
        }
#pragma unroll
    for (int mt = 0; mt < 2; mt++)
#pragma unroll
        for (int nc = 0; nc < 4; nc++) {
            int col = warp * 32 + nc * 8 + 2 * q;
            float2 v0 = make_float2(
                fmaxf(acc[mt][nc][0] * gsc[mt][0] + gsh[mt][0], 0.f),
                fmaxf(acc[mt][nc][1] * gsc[mt][0] + gsh[mt][0], 0.f));
            float2 v1 = make_float2(
                fmaxf(acc[mt][nc][2] * gsc[mt][1] + gsh[mt][1], 0.f),
                fmaxf(acc[mt][nc][3] * gsc[mt][1] + gsh[mt][1], 0.f));
            *(float2*)&y_s[(mt * 16 + r) * 264 + col]     = v0;
            *(float2*)&y_s[(mt * 16 + r + 8) * 264 + col] = v1;
        }
    __syncthreads();

    if (sel == 1) {
        // g: bf16 k-pair packed [b][k/2][m]
        uint32_t* op = g_g16 + (size_t)b * 16 * HW + p0;
#pragma unroll
        for (int j = 0; j < 16; j++) {
            int e = tid + 256 * j;
            int oc2 = e >> 8, pix = e & 255;
            float v0 = y_s[(2 * oc2) * 264 + pix];
            float v1 = y_s[(2 * oc2 + 1) * 264 + pix];
            op[(size_t)oc2 * HW + pix] = pkbf(v0, v1);
        }
        return;
    }

    // pooled writes (bf16, flash fragment order)
    int PR0 = p0 >> 7;
    if (sel == 0) {
        __nv_bfloat16* outp = (__nv_bfloat16*)(g_f16 + (size_t)b * 16384);
#pragma unroll
        for (int j = 0; j < 8; j++) {
            int e = tid + 256 * j;
            int ocl = e >> 6, qq = e & 63;
            int pq = qq >> 5, col = qq & 31;
            int base = ocl * 264 + pq * 128 + 2 * col;
            float v01 = fmaxf(y_s[base],      y_s[base + 1]);
            float v23 = fmaxf(y_s[base + 64], y_s[base + 65]);
            float v = fmaxf(v01, v23);
            int k = ocl, n = col, nt = PR0 + pq;
            int kc = k >> 4, kk = k & 15;
            int t = kk >> 3, kq = (kk >> 1) & 3, half = kk & 1;
            int ln = (n & 7) * 4 + kq, nc = n >> 3;
            int idx = (nt * 512 + ((nc * 2 + kc) * 32 + ln) * 2 + t) * 2 + half;
            outp[idx] = __float2bfloat16(v);
        }
    } else {
        __nv_bfloat16* outp = (__nv_bfloat16*)(g_hh16 + (size_t)b * 65536);
#pragma unroll
        for (int j = 0; j < 8; j++) {
            int e = tid + 256 * j;
            int ocl = e >> 6, qq = e & 63;
            int pq = qq >> 5, col = qq & 31;
            int base = ocl * 264 + pq * 128 + 2 * col;
            float v01 = fmaxf(y_s[base],      y_s[base + 1]);
            float v23 = fmaxf(y_s[base + 64], y_s[base + 65]);
            float v = fmaxf(v01, v23);
            int c = oc0 + ocl, n = col, nt = PR0 + pq;
            int kc = n >> 4, kk = n & 15;
            int t = kk >> 3, kq = (kk >> 1) & 3, half = kk & 1;
            int ln = (c & 7) * 4 + kq, cc = c >> 3;
            int idx = (nt * 2048 + ((cc * 2 + kc) * 32 + ln) * 2 + t) * 2 + half;
            outp[idx] = __float2bfloat16(v);
        }
    }
}

// ---------------------------------------------------------------------------
// Kernel 2: flash attention, bf16 m16n8k16. p never leaves registers
// (QK C-layout pairs == PV A-layout pairs). cp.async double-buffered fills.
// Dynamic smem: fB[2][512] + hB[2][2048] = 20 KB.
// ---------------------------------------------------------------------------
#define FL2_FB    0
#define FL2_HB    1024
#define FL2_WORDS 5120

__global__ __launch_bounds__(256) void flash_mma_kernel()
{
    extern __shared__ __align__(16) uint32_t dyn[];
    uint32_t smem0 = (uint32_t)__cvta_generic_to_shared(dyn);

    int b = blockIdx.y, m0 = blockIdx.x * 128;
    int tid  = threadIdx.x;
    int lane = tid & 31, warp = tid >> 5;
    int q = lane & 3, r = lane >> 2;

    const uint4* fsrc = (const uint4*)(g_f16  + (size_t)b * 16384);
    const uint4* hsrc = (const uint4*)(g_hh16 + (size_t)b * 65536);

    {   // prologue: tile 0 -> buf 0
        if (tid < 128)
            cp16(smem0 + ((uint32_t)(FL2_FB + tid * 4) << 2), &fsrc[tid]);
#pragma unroll
        for (int j = 0; j < 2; j++)
            cp16(smem0 + ((uint32_t)(FL2_HB + (tid + 256 * j) * 4) << 2),
                 &hsrc[tid + 256 * j]);
        CP_COMMIT();
    }

    // g A-fragments (bf16 pairs, tile-invariant): A[m][k] = g[k][m]
    const uint32_t* gb = g_g16 + (size_t)b * 16 * HW + m0 + warp * 16;
    uint32_t gA[2][4];
#pragma unroll
    for (int kc = 0; kc < 2; kc++) {
        gA[kc][0] = gb[(size_t)(kc * 8 + q)     * HW + r];
        gA[kc][1] = gb[(size_t)(kc * 8 + q)     * HW + r + 8];
        gA[kc][2] = gb[(size_t)(kc * 8 + q + 4) * HW + r];
        gA[kc][3] = gb[(size_t)(kc * 8 + q + 4) * HW + r + 8];
    }

    float mx0 = -INFINITY, mx1 = -INFINITY, l0 = 0.f, l1 = 0.f;
    float acc[16][4];
#pragma unroll
    for (int cc = 0; cc < 16; cc++)
#pragma unroll
        for (int i = 0; i < 4; i++) acc[cc][i] = 0.f;

    int buf = 0;
    for (int nt = 0; nt < 32; nt++) {
        if (nt < 31) {
            int nb = buf ^ 1;
            if (tid < 128)
                cp16(smem0 + ((uint32_t)(FL2_FB + nb * 512 + tid * 4) << 2),
                     &fsrc[(nt + 1) * 128 + tid]);
#pragma unroll
            for (int j = 0; j < 2; j++)
                cp16(smem0 + ((uint32_t)(FL2_HB + nb * 2048 + (tid + 256 * j) * 4) << 2),
                     &hsrc[(nt + 1) * 512 + tid + 256 * j]);
            CP_COMMIT();
            CP_WAIT1();
        } else {
            CP_WAIT0();
        }
        __syncthreads();

        const uint32_t* fBb = dyn + FL2_FB + buf * 512;
        const uint32_t* hBb = dyn + FL2_HB + buf * 2048;

        // ---- QK: sT[16m x 32n] per warp (8 MMAs)
        float s[4][4];
#pragma unroll
        for (int nc = 0; nc < 4; nc++)
#pragma unroll
            for (int i = 0; i < 4; i++) s[nc][i] = 0.f;
#pragma unroll
        for (int nc = 0; nc < 4; nc++)
#pragma unroll
            for (int kc = 0; kc < 2; kc++) {
                uint2 f = *(const uint2*)&fBb[((nc * 2 + kc) * 32 + lane) * 2];
                mma_bf16(s[nc], gA[kc], f.x, f.y);
            }

        // ---- row max (rows r, r+8), quad reduction
        float t0 = fmaxf(fmaxf(s[0][0], s[0][1]), fmaxf(s[1][0], s[1][1]));
        t0 = fmaxf(t0, fmaxf(fmaxf(s[2][0], s[2][1]), fmaxf(s[3][0], s[3][1])));
        float t1 = fmaxf(fmaxf(s[0][2], s[0][3]), fmaxf(s[1][2], s[1][3]));
        t1 = fmaxf(t1, fmaxf(fmaxf(s[2][2], s[2][3]), fmaxf(s[3][2], s[3][3])));
        t0 = fmaxf(t0, __shfl_xor_sync(0xffffffffu, t0, 1));
        t0 = fmaxf(t0, __shfl_xor_sync(0xffffffffu, t0, 2));
        t1 = fmaxf(t1, __shfl_xor_sync(0xffffffffu, t1, 1));
        t1 = fmaxf(t1, __shfl_xor_sync(0xffffffffu, t1, 2));
        float nm0 = fmaxf(mx0, t0), nm1 = fmaxf(mx1, t1);
        float fac0 = __expf(mx0 - nm0), fac1 = __expf(mx1 - nm1);
        mx0 = nm0; mx1 = nm1;

        // ---- exp (registers only) + partial row sums
        float e[4][4];
        float ps0 = 0.f, ps1 = 0.f;
#pragma unroll
        for (int nc = 0; nc < 4; nc++) {
            e[nc][0] = __expf(s[nc][0] - mx0);
            e[nc][1] = __expf(s[nc][1] - mx0);
            e[nc][2] = __expf(s[nc][2] - mx1);
            e[nc][3] = __expf(s[nc][3] - mx1);
            ps0 += e[nc][0] + e[nc][1];
            ps1 += e[nc][2] + e[nc][3];
        }
        ps0 += __shfl_xor_sync(0xffffffffu, ps0, 1);
        ps0 += __shfl_xor_sync(0xffffffffu, ps0, 2);
        ps1 += __shfl_xor_sync(0xffffffffu, ps1, 1);
        ps1 += __shfl_xor_sync(0xffffffffu, ps1, 2);
        l0 = l0 * fac0 + ps0;
        l1 = l1 * fac1 + ps1;

        // ---- pack p A-fragments directly from registers (no smem!)
        uint32_t pA[2][4];
#pragma unroll
        for (int kc = 0; kc < 2; kc++) {
            pA[kc][0] = pkbf(e[2 * kc][0],     e[2 * kc][1]);
            pA[kc][1] = pkbf(e[2 * kc][2],     e[2 * kc][3]);
            pA[kc][2] = pkbf(e[2 * kc + 1][0], e[2 * kc + 1][1]);
            pA[kc][3] = pkbf(e[2 * kc + 1][2], e[2 * kc + 1][3]);
        }

        // ---- rescale accumulator only if a row max changed
        bool need = (fac0 != 1.f) || (fac1 != 1.f);
        if (__any_sync(0xffffffffu, need)) {
#pragma unroll
            for (int cc = 0; cc < 16; cc++) {
                acc[cc][0] *= fac0; acc[cc][1] *= fac0;
                acc[cc][2] *= fac1; acc[cc][3] *= fac1;
            }
        }

        // ---- PV: oT[16m x 128c] += p[16m x 32n] * hhT[32n x 128c] (32 MMAs)
#pragma unroll
        for (int cc = 0; cc < 16; cc++)
#pragma unroll
            for (int kc = 0; kc < 2; kc++) {
                uint2 h = *(const uint2*)&hBb[((cc * 2 + kc) * 32 + lane) * 2];
                mma_bf16(acc[cc], pA[kc], h.x, h.y);
            }
        __syncthreads();
        buf ^= 1;
    }

    float rl0 = 1.f / l0, rl1 = 1.f / l1;
    float* ot = g_oT + ((size_t)b * HW + m0 + warp * 16) * 128;
#pragma unroll
    for (int cc = 0; cc < 16; cc++) {
        int c = cc * 8 + 2 * q;
        *(float2*)&ot[(size_t)r * 128 + c] =
            make_float2(acc[cc][0] * rl0, acc[cc][1] * rl0);
        *(float2*)&ot[(size_t)(r + 8) * 128 + c] =
            make_float2(acc[cc][2] * rl1, acc[cc][3] * rl1);
    }
}

// ---------------------------------------------------------------------------
// Kernel 3: out = gamma * BN(conv4(o)) + x (tf32, unchanged from round 12).
// ---------------------------------------------------------------------------
#define C4_WSTR 4608
#define C4_OSTR 2304
#define C4_OOFF 9216
#define C4_WORDS (C4_OOFF + 2 * C4_OSTR)

__global__ __launch_bounds__(256) void conv4_mma_kernel(
    const float* __restrict__ x,
    const float* __restrict__ w4, const float* __restrict__ b4, const float* __restrict__ s4,
    const float* __restrict__ t4, const float* __restrict__ m4, const float* __restrict__ v4,
    const float* __restrict__ gamma, float* __restrict__ out)
{
    extern __shared__ __align__(16) uint32_t dyn[];
    uint32_t* w4_s = dyn;
    uint32_t* o_s  = dyn + C4_OOFF;
    uint32_t smem0 = (uint32_t)__cvta_generic_to_shared(dyn);

    int b = blockIdx.z, oc0 = blockIdx.y * 128, p0 = blockIdx.x * 64;
    int tid = threadIdx.x, lane = tid & 31, warp = tid >> 5;
    int q = lane & 3, r = lane >> 2;

    const float* obT = g_oT + (size_t)b * HW * 128 + (size_t)p0 * 128;

    float acc[8][4];
#pragma unroll
    for (int nc = 0; nc < 8; nc++)
#pragma unroll
        for (int i = 0; i < 4; i++) acc[nc][i] = 0.f;

    {
#pragma unroll
        for (int j = 0; j < 4; j++) {
            int e = tid + 256 * j;
            int oc = e >> 3, kg = e & 7;
            cp16(smem0 + ((uint32_t)(oc * 36 + kg * 4) << 2),
                 &w4[(size_t)(oc0 + oc) * 128 + kg * 4]);
        }
#pragma unroll
        for (int j = 0; j < 2; j++) {
            int e = tid + 256 * j;
            int n = e >> 3, kg = e & 7;
            cp16(smem0 + ((uint32_t)(C4_OOFF + n * 36 + kg * 4) << 2),
                 &obT[(size_t)n * 128 + kg * 4]);
        }
        CP_COMMIT();
    }

    int buf = 0;
    for (int c = 0; c < 4; c++) {
        if (c < 3) {
            int nb = buf ^ 1;
#pragma unroll
            for (int j = 0; j < 4; j++) {
                int e = tid + 256 * j;
                int oc = e >> 3, kg = e & 7;
                cp16(smem0 + ((uint32_t)(nb * C4_WSTR + oc * 36 + kg * 4) << 2),
                     &w4[(size_t)(oc0 + oc) * 128 + (c + 1) * 32 + kg * 4]);
            }
#pragma unroll
            for (int j = 0; j < 2; j++) {
                int e = tid + 256 * j;
                int n = e >> 3, kg = e & 7;
                cp16(smem0 + ((uint32_t)(C4_OOFF + nb * C4_OSTR + n * 36 + kg * 4) << 2),
                     &obT[(size_t)n * 128 + (c + 1) * 32 + kg * 4]);
            }
            CP_COMMIT();
            CP_WAIT1();
        } else {
            CP_WAIT0();
        }
        __syncthreads();

        const uint32_t* wb = w4_s + buf * C4_WSTR;
        const uint32_t* ob = o_s + buf * C4_OSTR;
#pragma unroll
        for (int kc = 0; kc < 4; kc++) {
            uint32_t a[4];
            a[0] = wb[(warp * 16 + r) * 36 + kc * 8 + q];
            a[1] = wb[(warp * 16 + r + 8) * 36 + kc * 8 + q];
            a[2] = wb[(warp * 16 + r) * 36 + kc * 8 + q + 4];
            a[3] = wb[(warp * 16 + r + 8) * 36 + kc * 8 + q + 4];
#pragma unroll
            for (int nc = 0; nc < 8; nc++) {
                uint32_t bb0 = ob[(nc * 8 + r) * 36 + kc * 8 + q];
                uint32_t bb1 = ob[(nc * 8 + r) * 36 + kc * 8 + q + 4];
                mma_tf32(acc[nc], a, bb0, bb1);
            }
        }
        __syncthreads();
        buf ^= 1;
    }

    float gm = *gamma;
    int ocA = oc0 + warp * 16 + r, ocB = ocA + 8;
    float scA = s4[ocA] * rsqrtf(v4[ocA] + EPSV);
    float shA = (b4[ocA] - m4[ocA]) * scA + t4[ocA];
    float scB = s4[ocB] * rsqrtf(v4[ocB] + EPSV);
    float shB = (b4[ocB] - m4[ocB]) * scB + t4[ocB];
    const float* xpA = x   + ((size_t)b * CC + ocA) * HW + p0;
    float*       opA = out + ((size_t)b * CC + ocA) * HW + p0;
    const float* xpB = xpA + 8 * HW;
    float*       opB = opA + 8 * HW;
#pragma unroll
    for (int nc = 0; nc < 8; nc++) {
        int pix = nc * 8 + 2 * q;
        *(float2*)&opA[pix] = make_float2(
            gm * (acc[nc][0] * scA + shA) + xpA[pix],
            gm * (acc[nc][1] * scA + shA) + xpA[pix + 1]);
        *(float2*)&opB[pix] = make_float2(
            gm * (acc[nc][2] * scB + shB) + xpB[pix],
            gm * (acc[nc][3] * scB + shB) + xpB[pix + 1]);
    }
}

// ---------------------------------------------------------------------------
extern "C" void kernel_launch(void* const* d_in, const int* in_sizes, int n_in,
                              void* d_out, int out_size)
{
    (void)in_sizes; (void)n_in; (void)out_size;
    const float* x = (const float*)d_in[0];
#define P(i) ((const float*)d_in[i])

    cudaFuncSetAttribute(conv123_mma_kernel, cudaFuncAttributeMaxDynamicSharedMemorySize,
                         C1_WORDS * 4);
    cudaFuncSetAttribute(conv4_mma_kernel, cudaFuncAttributeMaxDynamicSharedMemorySize,
                         C4_WORDS * 4);

    conv123_mma_kernel<<<dim3(16, 6, 8), 256, C1_WORDS * 4>>>(
        x,
        P(1), P(2), P(3), P(4), P(5), P(6),        // conv1
        P(7), P(8), P(9), P(10), P(11), P(12),     // conv2
        P(13), P(14), P(15), P(16), P(17), P(18)); // conv3

    flash_mma_kernel<<<dim3(32, 8), 256, FL2_WORDS * 4>>>();

    conv4_mma_kernel<<<dim3(64, 2, 8), 256, C4_WORDS * 4>>>(
        x, P(19), P(20), P(21), P(22), P(23), P(24), P(25), (float*)d_out);
#undef P
}